// round 1
// baseline (speedup 1.0000x reference)
#include <cuda_runtime.h>
#include <cuda_bf16.h>
#include <math.h>

// Problem constants
#define BB 2
#define LQ 512
#define LK 2048
#define DM 1024
#define NH 16
#define HD 64
#define SCALE 0.125f
#define NTOP 31

// ---------------- scratch (device globals; no allocations allowed) ----------
__device__ float g_Q[BB * LQ * DM];        // 4 MB
__device__ float g_K[BB * LK * DM];        // 16 MB
__device__ float g_V[BB * LK * DM];        // 16 MB
__device__ float g_bout[BB * LQ * DM];     // 4 MB  (branch output, merged layout)
__device__ float g_proj[BB * LQ * DM];     // 4 MB  (branch @ Wo)
__device__ float g_kv[BB * NH * HD * HD];  // 0.5 MB
__device__ float g_ksum[BB * NH * HD];
__device__ float g_M[BB * NH * LQ];
__device__ int   g_top[BB * NH * NTOP];
__device__ float g_vmean[BB * NH * HD];

// ---------------- helpers ---------------------------------------------------
__device__ __forceinline__ float branch_weight(const float* __restrict__ alphas, int idx) {
    float mx = -1e30f;
    #pragma unroll
    for (int i = 0; i < 6; i++) mx = fmaxf(mx, alphas[i]);
    float s = 0.f;
    #pragma unroll
    for (int i = 0; i < 6; i++) s += expf(alphas[i] - mx);
    return expf(alphas[idx] - mx) / s;
}

// ---------------- generic row-major SGEMM: C[M,N] = A[M,K] * B[K,N] ---------
#define TM 64
#define TN 64
#define TK 16
__global__ void sgemm_kernel(const float* __restrict__ A, const float* __restrict__ B,
                             float* __restrict__ C, int M, int N, int K) {
    __shared__ float As[TK][TM];
    __shared__ float Bs[TK][TN];
    const int bm = blockIdx.y * TM;
    const int bn = blockIdx.x * TN;
    const int tid = threadIdx.x;           // 256 threads
    const int tr = tid / 16;               // 0..15
    const int tc = tid % 16;               // 0..15
    float acc[4][4];
    #pragma unroll
    for (int i = 0; i < 4; i++)
        #pragma unroll
        for (int j = 0; j < 4; j++) acc[i][j] = 0.f;

    for (int k0 = 0; k0 < K; k0 += TK) {
        #pragma unroll
        for (int i = tid; i < TM * TK; i += 256) {
            int m = i / TK, kk = i % TK;
            As[kk][m] = A[(size_t)(bm + m) * K + k0 + kk];
        }
        #pragma unroll
        for (int i = tid; i < TK * TN; i += 256) {
            int kk = i / TN, n = i % TN;
            Bs[kk][n] = B[(size_t)(k0 + kk) * N + bn + n];
        }
        __syncthreads();
        #pragma unroll
        for (int kk = 0; kk < TK; kk++) {
            float a[4], b[4];
            #pragma unroll
            for (int i = 0; i < 4; i++) a[i] = As[kk][tr * 4 + i];
            #pragma unroll
            for (int j = 0; j < 4; j++) b[j] = Bs[kk][tc * 4 + j];
            #pragma unroll
            for (int i = 0; i < 4; i++)
                #pragma unroll
                for (int j = 0; j < 4; j++) acc[i][j] += a[i] * b[j];
        }
        __syncthreads();
    }
    #pragma unroll
    for (int i = 0; i < 4; i++)
        #pragma unroll
        for (int j = 0; j < 4; j++)
            C[(size_t)(bm + tr * 4 + i) * N + bn + tc * 4 + j] = acc[i][j];
}

// ---------------- fused softmax attention (SDP / local / probsparse-top) ----
// one block (128 threads) per query row
__global__ void attn_kernel(const float* __restrict__ Qp, const float* __restrict__ Kp,
                            const float* __restrict__ Vp, float* __restrict__ bout,
                            const int* __restrict__ row_map, int windowed) {
    const int b = blockIdx.z, h = blockIdx.y;
    int t = blockIdx.x;
    if (row_map) t = row_map[(b * NH + h) * NTOP + blockIdx.x];

    int lo = 0, hi = LK - 1;
    if (windowed) {
        int center = min(4 * t, LK - 1);
        lo = max(center - 256, 0);
        hi = min(center + 256, LK - 1);
    }

    __shared__ __align__(16) float sh_q[HD];
    __shared__ float sh_sc[LK];
    __shared__ float sh_red[128];
    __shared__ float sh_acc[128 * 65];

    const int tid = threadIdx.x;
    if (tid < HD)
        sh_q[tid] = Qp[((size_t)(b * LQ + t)) * DM + h * HD + tid];
    __syncthreads();

    const float4* q4 = reinterpret_cast<const float4*>(sh_q);

    // phase 1: scores + local max
    float lmax = -1e30f;
    for (int s = lo + tid; s <= hi; s += 128) {
        const float4* k4 = reinterpret_cast<const float4*>(
            Kp + ((size_t)(b * LK + s)) * DM + h * HD);
        float d = 0.f;
        #pragma unroll
        for (int j = 0; j < 16; j++) {
            float4 a = q4[j], kk = k4[j];
            d += a.x * kk.x + a.y * kk.y + a.z * kk.z + a.w * kk.w;
        }
        float sc = d * SCALE;
        sh_sc[s - lo] = sc;
        lmax = fmaxf(lmax, sc);
    }
    sh_red[tid] = lmax;
    __syncthreads();
    #pragma unroll
    for (int o = 64; o > 0; o >>= 1) {
        if (tid < o) sh_red[tid] = fmaxf(sh_red[tid], sh_red[tid + o]);
        __syncthreads();
    }
    const float m = sh_red[0];
    __syncthreads();

    // phase 2: exp, denominator, weighted V accumulation
    float lsum = 0.f;
    float4 acc[16];
    #pragma unroll
    for (int j = 0; j < 16; j++) acc[j] = make_float4(0.f, 0.f, 0.f, 0.f);
    for (int s = lo + tid; s <= hi; s += 128) {
        float p = expf(sh_sc[s - lo] - m);
        lsum += p;
        const float4* v4 = reinterpret_cast<const float4*>(
            Vp + ((size_t)(b * LK + s)) * DM + h * HD);
        #pragma unroll
        for (int j = 0; j < 16; j++) {
            float4 v = v4[j];
            acc[j].x += p * v.x; acc[j].y += p * v.y;
            acc[j].z += p * v.z; acc[j].w += p * v.w;
        }
    }
    sh_red[tid] = lsum;
    __syncthreads();
    #pragma unroll
    for (int o = 64; o > 0; o >>= 1) {
        if (tid < o) sh_red[tid] += sh_red[tid + o];
        __syncthreads();
    }
    const float denom = sh_red[0];

    #pragma unroll
    for (int j = 0; j < 16; j++) {
        sh_acc[tid * 65 + j * 4 + 0] = acc[j].x;
        sh_acc[tid * 65 + j * 4 + 1] = acc[j].y;
        sh_acc[tid * 65 + j * 4 + 2] = acc[j].z;
        sh_acc[tid * 65 + j * 4 + 3] = acc[j].w;
    }
    __syncthreads();
    if (tid < HD) {
        float r = 0.f;
        #pragma unroll 8
        for (int i = 0; i < 128; i++) r += sh_acc[i * 65 + tid];
        bout[((size_t)(b * LQ + t)) * DM + h * HD + tid] = r / denom;
    }
}

// ---------------- linear / cosine: KV aggregation ---------------------------
// mode 0 = linear (elu(k)+1), mode 1 = cosine (relu(k/||k||)+1e-6)
__global__ void kv_kernel(const float* __restrict__ Kp, const float* __restrict__ Vp,
                          float* __restrict__ kvout, float* __restrict__ ksumout,
                          int mode) {
    const int b = blockIdx.z, h = blockIdx.y;
    __shared__ float sk[32][HD];
    __shared__ float sv[32][HD];
    __shared__ float snorm[32];
    const int tid = threadIdx.x;           // 256
    const int dmy = tid / 4;               // 0..63
    const int vg = tid % 4;                // v base = vg*16
    float acc[16];
    #pragma unroll
    for (int j = 0; j < 16; j++) acc[j] = 0.f;
    float ksacc = 0.f;

    for (int s0 = 0; s0 < LK; s0 += 32) {
        for (int i = tid; i < 32 * HD; i += 256) {
            int ss = i / HD, dd = i % HD;
            size_t base = ((size_t)(b * LK + s0 + ss)) * DM + h * HD + dd;
            sk[ss][dd] = Kp[base];
            sv[ss][dd] = Vp[base];
        }
        __syncthreads();
        if (mode == 1 && tid < 32) {
            float n = 0.f;
            #pragma unroll
            for (int j = 0; j < HD; j++) n += sk[tid][j] * sk[tid][j];
            snorm[tid] = fmaxf(sqrtf(n), 1e-12f);
        }
        __syncthreads();
        #pragma unroll 4
        for (int ss = 0; ss < 32; ss++) {
            float kval = sk[ss][dmy];
            float kf;
            if (mode == 0) kf = (kval > 0.f) ? (kval + 1.f) : expf(kval);
            else {
                float kn = kval / snorm[ss];
                kf = ((kn > 0.f) ? kn : 0.f) + 1e-6f;
            }
            if (vg == 0) ksacc += kf;
            #pragma unroll
            for (int j = 0; j < 16; j++) acc[j] += kf * sv[ss][vg * 16 + j];
        }
        __syncthreads();
    }
    const int bh = b * NH + h;
    #pragma unroll
    for (int j = 0; j < 16; j++)
        kvout[((size_t)bh * HD + dmy) * HD + vg * 16 + j] = acc[j];
    if (vg == 0) ksumout[bh * HD + dmy] = ksacc;
}

// ---------------- linear / cosine: output -----------------------------------
__global__ void lin_out_kernel(const float* __restrict__ Qp, const float* __restrict__ kv,
                               const float* __restrict__ ksum, float* __restrict__ bout,
                               int mode) {
    const int b = blockIdx.z, h = blockIdx.y, t = blockIdx.x;
    __shared__ float sqf[HD];
    __shared__ float red[HD];
    const int tid = threadIdx.x;           // 64
    float qv = Qp[((size_t)(b * LQ + t)) * DM + h * HD + tid];
    if (mode == 0) {
        float x = qv * SCALE;
        sqf[tid] = (x > 0.f) ? (x + 1.f) : expf(x);
    } else {
        red[tid] = qv * qv;
        __syncthreads();
        #pragma unroll
        for (int o = 32; o > 0; o >>= 1) {
            if (tid < o) red[tid] += red[tid + o];
            __syncthreads();
        }
        float nrm = fmaxf(sqrtf(red[0]), 1e-12f);
        float qn = qv / nrm;
        sqf[tid] = ((qn > 0.f) ? qn : 0.f) + 1e-6f;
    }
    __syncthreads();
    const int bh = b * NH + h;
    const float* kvb = kv + (size_t)bh * HD * HD;
    const float* ksb = ksum + (size_t)bh * HD;
    float accv = 0.f, den = 0.f;
    #pragma unroll 8
    for (int d = 0; d < HD; d++) {
        float qf = sqf[d];
        accv += qf * kvb[d * HD + tid];
        den += qf * ksb[d];
    }
    den = fmaxf(den, 1e-6f);
    bout[((size_t)(b * LQ + t)) * DM + h * HD + tid] = accv / den;
}

// ---------------- probsparse: sparsity measure M ----------------------------
__global__ void psparse_m_kernel(const float* __restrict__ Qp, const float* __restrict__ Kp,
                                 const int* __restrict__ sidx, int nsample,
                                 float* __restrict__ Mout) {
    const int b = blockIdx.z, h = blockIdx.y;
    __shared__ float sks[64 * HD];         // up to 64 sampled keys
    const int tid = threadIdx.x;           // 128
    for (int i = tid; i < nsample * HD; i += 128) {
        int j = i / HD, dd = i % HD;
        sks[i] = Kp[((size_t)(b * LK + sidx[j])) * DM + h * HD + dd];
    }
    __syncthreads();
    const int t = blockIdx.x * 128 + tid;
    float qr[HD];
    const float* qrow = Qp + ((size_t)(b * LQ + t)) * DM + h * HD;
    #pragma unroll
    for (int j = 0; j < HD; j++) qr[j] = qrow[j];
    float mx = -1e30f, sm = 0.f;
    for (int j = 0; j < nsample; j++) {
        float d = 0.f;
        #pragma unroll
        for (int dd = 0; dd < HD; dd++) d += qr[dd] * sks[j * HD + dd];
        mx = fmaxf(mx, d);
        sm += d;
    }
    Mout[((size_t)(b * NH + h)) * LQ + t] = SCALE * (mx - sm / (float)nsample);
}

// ---------------- probsparse: top-k selection -------------------------------
__global__ void topk_kernel(const float* __restrict__ M, int* __restrict__ topidx) {
    const int bh = blockIdx.x;
    __shared__ float vals[LQ];
    __shared__ float rv[256];
    __shared__ int ri[256];
    const int tid = threadIdx.x;           // 256
    vals[tid] = M[(size_t)bh * LQ + tid];
    vals[tid + 256] = M[(size_t)bh * LQ + tid + 256];
    __syncthreads();
    for (int it = 0; it < NTOP; it++) {
        float v1 = vals[tid], v2 = vals[tid + 256];
        float bv; int bi;
        if (v1 >= v2) { bv = v1; bi = tid; } else { bv = v2; bi = tid + 256; }
        rv[tid] = bv; ri[tid] = bi;
        __syncthreads();
        #pragma unroll
        for (int o = 128; o > 0; o >>= 1) {
            if (tid < o) {
                if (rv[tid + o] > rv[tid] ||
                    (rv[tid + o] == rv[tid] && ri[tid + o] < ri[tid])) {
                    rv[tid] = rv[tid + o];
                    ri[tid] = ri[tid + o];
                }
            }
            __syncthreads();
        }
        if (tid == 0) {
            topidx[bh * NTOP + it] = ri[0];
            vals[ri[0]] = -1e30f;
        }
        __syncthreads();
    }
}

// ---------------- probsparse: v mean + fill ---------------------------------
__global__ void vmean_kernel(const float* __restrict__ Vp, float* __restrict__ vmean) {
    const int bh = blockIdx.x;
    const int b = bh / NH, h = bh % NH;
    const int tid = threadIdx.x;           // 64
    float s = 0.f;
    for (int ss = 0; ss < LK; ss++)
        s += Vp[((size_t)(b * LK + ss)) * DM + h * HD + tid];
    vmean[bh * HD + tid] = s * (1.0f / LK);
}

__global__ void fill_vmean_kernel(const float* __restrict__ vmean, float* __restrict__ bout) {
    const int idx = blockIdx.x * 256 + threadIdx.x;
    if (idx >= BB * LQ * DM) return;
    const int d = idx % DM;
    const int bt = idx / DM;
    const int b = bt / LQ;
    const int h = d / HD, dh = d % HD;
    bout[idx] = vmean[(b * NH + h) * HD + dh];
}

// ---------------- epilogues -------------------------------------------------
__global__ void init_out_kernel(const float* __restrict__ dec,
                                const float* __restrict__ alphas,
                                float* __restrict__ out) {
    const int idx = blockIdx.x * 256 + threadIdx.x;
    if (idx >= BB * LQ * DM) return;
    float w0 = branch_weight(alphas, 0);
    out[idx] = w0 * dec[idx];
}

__global__ void rms_accum_kernel(const float* __restrict__ dec, const float* __restrict__ proj,
                                 const float* __restrict__ rms_w, const float* __restrict__ alphas,
                                 int widx, float* __restrict__ out) {
    const int row = blockIdx.x;            // B*LQ rows
    const int tid = threadIdx.x;           // 256
    __shared__ float red[256];
    __shared__ float sw;
    if (tid == 0) sw = branch_weight(alphas, widx);
    float ss = 0.f;
    const size_t base = (size_t)row * DM;
    for (int d = tid; d < DM; d += 256) {
        float x = dec[base + d] + proj[base + d];
        ss += x * x;
    }
    red[tid] = ss;
    __syncthreads();
    #pragma unroll
    for (int o = 128; o > 0; o >>= 1) {
        if (tid < o) red[tid] += red[tid + o];
        __syncthreads();
    }
    const float rs = rsqrtf(red[0] / (float)DM + 1e-6f);
    const float w = sw;
    for (int d = tid; d < DM; d += 256) {
        float x = dec[base + d] + proj[base + d];
        out[base + d] += w * x * rs * rms_w[d];
    }
}

// ---------------- launch ----------------------------------------------------
extern "C" void kernel_launch(void* const* d_in, const int* in_sizes, int n_in,
                              void* d_out, int out_size) {
    const float* dec   = (const float*)d_in[0];
    const float* enc   = (const float*)d_in[1];
    const float* Wq    = (const float*)d_in[2];
    const float* Wk    = (const float*)d_in[3];
    const float* Wv    = (const float*)d_in[4];
    const float* Wo    = (const float*)d_in[5];
    const float* rmsw  = (const float*)d_in[6];
    const float* alphas= (const float*)d_in[7];
    const int*   sidx  = (const int*)d_in[8];
    const int nsample  = in_sizes[8];
    float* out = (float*)d_out;

    float *Qs, *Ks, *Vs, *bo, *pj, *kv, *ks, *Mv, *vm;
    int* tp;
    cudaGetSymbolAddress((void**)&Qs, g_Q);
    cudaGetSymbolAddress((void**)&Ks, g_K);
    cudaGetSymbolAddress((void**)&Vs, g_V);
    cudaGetSymbolAddress((void**)&bo, g_bout);
    cudaGetSymbolAddress((void**)&pj, g_proj);
    cudaGetSymbolAddress((void**)&kv, g_kv);
    cudaGetSymbolAddress((void**)&ks, g_ksum);
    cudaGetSymbolAddress((void**)&Mv, g_M);
    cudaGetSymbolAddress((void**)&tp, g_top);
    cudaGetSymbolAddress((void**)&vm, g_vmean);

    const int MQ = BB * LQ;   // 1024
    const int MK = BB * LK;   // 4096
    dim3 gq(DM / TN, MQ / TM);   // (16,16)
    dim3 gk(DM / TN, MK / TM);   // (16,64)

    // projections
    sgemm_kernel<<<gq, 256>>>(dec, Wq, Qs, MQ, DM, DM);
    sgemm_kernel<<<gk, 256>>>(enc, Wk, Ks, MK, DM, DM);
    sgemm_kernel<<<gk, 256>>>(enc, Wv, Vs, MK, DM, DM);

    // out = w0 * dec
    init_out_kernel<<<(BB * LQ * DM + 255) / 256, 256>>>(dec, alphas, out);

    // ---- branch 1: SDP ----
    attn_kernel<<<dim3(LQ, NH, BB), 128>>>(Qs, Ks, Vs, bo, nullptr, 0);
    sgemm_kernel<<<gq, 256>>>(bo, Wo, pj, MQ, DM, DM);
    rms_accum_kernel<<<MQ, 256>>>(dec, pj, rmsw, alphas, 1, out);

    // ---- branch 2: linear ----
    kv_kernel<<<dim3(1, NH, BB), 256>>>(Ks, Vs, kv, ks, 0);
    lin_out_kernel<<<dim3(LQ, NH, BB), 64>>>(Qs, kv, ks, bo, 0);
    sgemm_kernel<<<gq, 256>>>(bo, Wo, pj, MQ, DM, DM);
    rms_accum_kernel<<<MQ, 256>>>(dec, pj, rmsw, alphas, 2, out);

    // ---- branch 3: probsparse ----
    psparse_m_kernel<<<dim3(LQ / 128, NH, BB), 128>>>(Qs, Ks, sidx, nsample, Mv);
    topk_kernel<<<BB * NH, 256>>>(Mv, tp);
    vmean_kernel<<<BB * NH, 64>>>(Vs, vm);
    fill_vmean_kernel<<<(BB * LQ * DM + 255) / 256, 256>>>(vm, bo);
    attn_kernel<<<dim3(NTOP, NH, BB), 128>>>(Qs, Ks, Vs, bo, tp, 0);
    sgemm_kernel<<<gq, 256>>>(bo, Wo, pj, MQ, DM, DM);
    rms_accum_kernel<<<MQ, 256>>>(dec, pj, rmsw, alphas, 3, out);

    // ---- branch 4: cosine ----
    kv_kernel<<<dim3(1, NH, BB), 256>>>(Ks, Vs, kv, ks, 1);
    lin_out_kernel<<<dim3(LQ, NH, BB), 64>>>(Qs, kv, ks, bo, 1);
    sgemm_kernel<<<gq, 256>>>(bo, Wo, pj, MQ, DM, DM);
    rms_accum_kernel<<<MQ, 256>>>(dec, pj, rmsw, alphas, 4, out);

    // ---- branch 5: local windowed ----
    attn_kernel<<<dim3(LQ, NH, BB), 128>>>(Qs, Ks, Vs, bo, nullptr, 1);
    sgemm_kernel<<<gq, 256>>>(bo, Wo, pj, MQ, DM, DM);
    rms_accum_kernel<<<MQ, 256>>>(dec, pj, rmsw, alphas, 5, out);
}

// round 3
// speedup vs baseline: 5.1327x; 5.1327x over previous
#include <cuda_runtime.h>
#include <cuda_bf16.h>
#include <math.h>

#define BB 2
#define LQ 512
#define LK 2048
#define DM 1024
#define NH 16
#define HD 64
#define SCALE 0.125f
#define NTOP 31
#define NBR 5
#define MROWS (BB * LQ)           // 1024

// ---------------- scratch ----------------------------------------------------
__device__ float g_Q[BB * LQ * DM];
__device__ float g_K[BB * LK * DM];
__device__ float g_V[BB * LK * DM];
__device__ float g_bout[NBR * MROWS * DM];    // 20 MB (5 branch outputs)
__device__ float g_proj[NBR * MROWS * DM];    // 20 MB
__device__ float g_kvpart[8 * BB * NH * HD * HD];
__device__ float g_kspart[8 * BB * NH * HD];
__device__ float g_kv[BB * NH * HD * HD];
__device__ float g_ksum[BB * NH * HD];
__device__ float g_M[BB * NH * LQ];
__device__ int   g_top[BB * NH * NTOP];
__device__ float g_vmean[BB * NH * HD];

// ---------------- SGEMM: C[M,N] = A[M,K] @ B[K,N], 128x128x16 ---------------
#define GBM 128
#define GBN 128
#define GBK 16
__global__ __launch_bounds__(256) void sgemm2(const float* __restrict__ A,
                                              const float* __restrict__ B,
                                              float* __restrict__ C,
                                              int M, int N, int K) {
    __shared__ float As[GBK][GBM];
    __shared__ float Bs[GBK][GBN];
    const int bm = blockIdx.y * GBM;
    const int bn = blockIdx.x * GBN;
    const int tid = threadIdx.x;
    const int tr = tid / 16, tc = tid % 16;
    const int arow = tid / 4;
    const int akc  = (tid % 4) * 4;
    const int brow = tid / 32;
    const int bcol = (tid % 32) * 4;

    float acc[8][8];
    #pragma unroll
    for (int i = 0; i < 8; i++)
        #pragma unroll
        for (int j = 0; j < 8; j++) acc[i][j] = 0.f;

    for (int k0 = 0; k0 < K; k0 += GBK) {
        float4 a0 = *(const float4*)(A + (size_t)(bm + arow) * K + k0 + akc);
        float4 a1 = *(const float4*)(A + (size_t)(bm + 64 + arow) * K + k0 + akc);
        float4 b0 = *(const float4*)(B + (size_t)(k0 + brow) * N + bn + bcol);
        float4 b1 = *(const float4*)(B + (size_t)(k0 + 8 + brow) * N + bn + bcol);
        __syncthreads();
        As[akc + 0][arow] = a0.x; As[akc + 1][arow] = a0.y;
        As[akc + 2][arow] = a0.z; As[akc + 3][arow] = a0.w;
        As[akc + 0][64 + arow] = a1.x; As[akc + 1][64 + arow] = a1.y;
        As[akc + 2][64 + arow] = a1.z; As[akc + 3][64 + arow] = a1.w;
        *(float4*)&Bs[brow][bcol] = b0;
        *(float4*)&Bs[8 + brow][bcol] = b1;
        __syncthreads();
        #pragma unroll
        for (int kk = 0; kk < GBK; kk++) {
            float4 xa0 = *(float4*)&As[kk][tr * 4];
            float4 xa1 = *(float4*)&As[kk][64 + tr * 4];
            float4 xb0 = *(float4*)&Bs[kk][tc * 4];
            float4 xb1 = *(float4*)&Bs[kk][64 + tc * 4];
            float av[8] = {xa0.x, xa0.y, xa0.z, xa0.w, xa1.x, xa1.y, xa1.z, xa1.w};
            float bv[8] = {xb0.x, xb0.y, xb0.z, xb0.w, xb1.x, xb1.y, xb1.z, xb1.w};
            #pragma unroll
            for (int i = 0; i < 8; i++)
                #pragma unroll
                for (int j = 0; j < 8; j++) acc[i][j] += av[i] * bv[j];
        }
    }
    #pragma unroll
    for (int i = 0; i < 8; i++) {
        int row = bm + ((i < 4) ? (tr * 4 + i) : (64 + tr * 4 + i - 4));
        float4 c0 = make_float4(acc[i][0], acc[i][1], acc[i][2], acc[i][3]);
        float4 c1 = make_float4(acc[i][4], acc[i][5], acc[i][6], acc[i][7]);
        *(float4*)(C + (size_t)row * N + bn + tc * 4) = c0;
        *(float4*)(C + (size_t)row * N + bn + 64 + tc * 4) = c1;
    }
}

// ---------------- flash attention: 64q x 64k tiles, online softmax ----------
// mode 0 = dense SDP, 1 = local windowed, 2 = row-gather (probsparse top)
#define FQ 64
#define FS 64
#define FP 68            // padded row stride (floats)
__global__ __launch_bounds__(256) void flash_kernel(const float* __restrict__ Qp,
                                                    const float* __restrict__ Kp,
                                                    const float* __restrict__ Vp,
                                                    float* __restrict__ bout,
                                                    const int* __restrict__ row_map,
                                                    int mode) {
    extern __shared__ float fsm[];
    float* Qs  = fsm;                  // [64][FP]
    float* KVs = fsm + FQ * FP;        // [64][FP]  K tile then V tile
    float* Ps  = fsm + 2 * FQ * FP;    // [64][FP]

    const int b = blockIdx.z, h = blockIdx.y;
    const int qbase = blockIdx.x * FQ;
    const int tid = threadIdx.x;
    const int ty = tid / 16, tx = tid % 16;

    // load Q tile (gathered in mode 2)
    #pragma unroll
    for (int r = 0; r < 4; r++) {
        int idx = r * 256 + tid;
        int q = idx / 16, dg = (idx % 16) * 4;
        int t; bool valid = true;
        if (mode == 2) {
            if (q < NTOP) t = row_map[(b * NH + h) * NTOP + q];
            else { t = 0; valid = false; }
        } else t = qbase + q;
        float4 v = valid ? *(const float4*)(Qp + ((size_t)(b * LQ + t)) * DM + h * HD + dg)
                         : make_float4(0.f, 0.f, 0.f, 0.f);
        *(float4*)&Qs[q * FP + dg] = v;
    }
    __syncthreads();

    float m_i[4], l_i[4], acc[4][4];
    #pragma unroll
    for (int i = 0; i < 4; i++) {
        m_i[i] = -1e30f; l_i[i] = 0.f;
        #pragma unroll
        for (int j = 0; j < 4; j++) acc[i][j] = 0.f;
    }

    int st_lo = 0, st_hi = LK / FS - 1;
    if (mode == 1) {
        int lo = max(0, 4 * qbase - 256);
        int hi = min(LK - 1, 4 * (qbase + FQ - 1) + 256);
        st_lo = lo / FS; st_hi = hi / FS;
    }

    for (int st = st_lo; st <= st_hi; st++) {
        const int s0 = st * FS;
        // load K tile
        #pragma unroll
        for (int r = 0; r < 4; r++) {
            int idx = r * 256 + tid;
            int s = idx / 16, dg = (idx % 16) * 4;
            *(float4*)&KVs[s * FP + dg] =
                *(const float4*)(Kp + ((size_t)(b * LK + s0 + s)) * DM + h * HD + dg);
        }
        __syncthreads();

        // scores: rows ty*4+i, keys tx+16*j
        float sc[4][4];
        #pragma unroll
        for (int i = 0; i < 4; i++)
            #pragma unroll
            for (int j = 0; j < 4; j++) sc[i][j] = 0.f;
        #pragma unroll
        for (int d4 = 0; d4 < 16; d4++) {
            float4 qv[4], kv[4];
            #pragma unroll
            for (int i = 0; i < 4; i++) qv[i] = *(float4*)&Qs[(ty * 4 + i) * FP + d4 * 4];
            #pragma unroll
            for (int j = 0; j < 4; j++) kv[j] = *(float4*)&KVs[(tx + 16 * j) * FP + d4 * 4];
            #pragma unroll
            for (int i = 0; i < 4; i++)
                #pragma unroll
                for (int j = 0; j < 4; j++)
                    sc[i][j] += qv[i].x * kv[j].x + qv[i].y * kv[j].y +
                                qv[i].z * kv[j].z + qv[i].w * kv[j].w;
        }
        #pragma unroll
        for (int i = 0; i < 4; i++)
            #pragma unroll
            for (int j = 0; j < 4; j++) sc[i][j] *= SCALE;

        if (mode == 1) {
            #pragma unroll
            for (int i = 0; i < 4; i++) {
                int t = qbase + ty * 4 + i;
                int center = min(4 * t, LK - 1);
                int lo = max(center - 256, 0);
                int hi = min(center + 256, LK - 1);
                #pragma unroll
                for (int j = 0; j < 4; j++) {
                    int s = s0 + tx + 16 * j;
                    if (s < lo || s > hi) sc[i][j] = -1e30f;
                }
            }
        }

        // online softmax update
        #pragma unroll
        for (int i = 0; i < 4; i++) {
            float rmax = fmaxf(fmaxf(sc[i][0], sc[i][1]), fmaxf(sc[i][2], sc[i][3]));
            #pragma unroll
            for (int off = 1; off < 16; off <<= 1)
                rmax = fmaxf(rmax, __shfl_xor_sync(0xffffffffu, rmax, off, 16));
            float nm = fmaxf(m_i[i], rmax);
            float corr = __expf(m_i[i] - nm);
            float rsum = 0.f;
            float p[4];
            #pragma unroll
            for (int j = 0; j < 4; j++) {
                p[j] = (sc[i][j] < -5e29f) ? 0.f : __expf(sc[i][j] - nm);
                rsum += p[j];
            }
            #pragma unroll
            for (int off = 1; off < 16; off <<= 1)
                rsum += __shfl_xor_sync(0xffffffffu, rsum, off, 16);
            l_i[i] = l_i[i] * corr + rsum;
            #pragma unroll
            for (int j = 0; j < 4; j++) acc[i][j] *= corr;
            m_i[i] = nm;
            #pragma unroll
            for (int j = 0; j < 4; j++)
                Ps[(ty * 4 + i) * FP + tx + 16 * j] = p[j];
        }
        __syncthreads();   // Ps written, K reads done

        // load V tile (reuse KVs)
        #pragma unroll
        for (int r = 0; r < 4; r++) {
            int idx = r * 256 + tid;
            int s = idx / 16, dg = (idx % 16) * 4;
            *(float4*)&KVs[s * FP + dg] =
                *(const float4*)(Vp + ((size_t)(b * LK + s0 + s)) * DM + h * HD + dg);
        }
        __syncthreads();

        // AV: dims tx*4+j
        #pragma unroll 8
        for (int s = 0; s < FS; s++) {
            float4 vv = *(float4*)&KVs[s * FP + tx * 4];
            #pragma unroll
            for (int i = 0; i < 4; i++) {
                float pi = Ps[(ty * 4 + i) * FP + s];
                acc[i][0] += pi * vv.x; acc[i][1] += pi * vv.y;
                acc[i][2] += pi * vv.z; acc[i][3] += pi * vv.w;
            }
        }
        __syncthreads();
    }

    // write
    #pragma unroll
    for (int i = 0; i < 4; i++) {
        int q = ty * 4 + i;
        int t;
        if (mode == 2) {
            if (q >= NTOP) continue;
            t = row_map[(b * NH + h) * NTOP + q];
        } else t = qbase + q;
        float inv = 1.f / l_i[i];
        float4 o = make_float4(acc[i][0] * inv, acc[i][1] * inv,
                               acc[i][2] * inv, acc[i][3] * inv);
        *(float4*)(bout + ((size_t)(b * LQ + t)) * DM + h * HD + tx * 4) = o;
    }
}

// ---------------- linear/cosine KV aggregation (chunked, deterministic) -----
__global__ void kvchunk_kernel(const float* __restrict__ Kp, const float* __restrict__ Vp,
                               float* __restrict__ kvpart, float* __restrict__ kspart,
                               int mode) {
    const int c = blockIdx.x, h = blockIdx.y, b = blockIdx.z;
    __shared__ float sk[32][HD];
    __shared__ float sv[32][HD];
    __shared__ float snorm[32];
    const int tid = threadIdx.x;
    const int dmy = tid / 4, vg = tid % 4;
    float acc[16];
    #pragma unroll
    for (int j = 0; j < 16; j++) acc[j] = 0.f;
    float ksacc = 0.f;
    const int sbeg = c * (LK / 8), send = sbeg + LK / 8;

    for (int s0 = sbeg; s0 < send; s0 += 32) {
        for (int i = tid; i < 32 * HD; i += 256) {
            int ss = i / HD, dd = i % HD;
            size_t base = ((size_t)(b * LK + s0 + ss)) * DM + h * HD + dd;
            sk[ss][dd] = Kp[base];
            sv[ss][dd] = Vp[base];
        }
        __syncthreads();
        if (mode == 1 && tid < 32) {
            float n = 0.f;
            #pragma unroll
            for (int j = 0; j < HD; j++) n += sk[tid][j] * sk[tid][j];
            snorm[tid] = fmaxf(sqrtf(n), 1e-12f);
        }
        __syncthreads();
        #pragma unroll 4
        for (int ss = 0; ss < 32; ss++) {
            float kval = sk[ss][dmy];
            float kf;
            if (mode == 0) kf = (kval > 0.f) ? (kval + 1.f) : __expf(kval);
            else {
                float kn = kval / snorm[ss];
                kf = ((kn > 0.f) ? kn : 0.f) + 1e-6f;
            }
            if (vg == 0) ksacc += kf;
            #pragma unroll
            for (int j = 0; j < 16; j++) acc[j] += kf * sv[ss][vg * 16 + j];
        }
        __syncthreads();
    }
    const int bh = b * NH + h;
    const int NKV = BB * NH * HD * HD;
    #pragma unroll
    for (int j = 0; j < 16; j++)
        kvpart[(size_t)c * NKV + ((size_t)bh * HD + dmy) * HD + vg * 16 + j] = acc[j];
    if (vg == 0) kspart[c * (BB * NH * HD) + bh * HD + dmy] = ksacc;
}

__global__ void kvreduce_kernel(const float* __restrict__ part, float* __restrict__ outp, int n) {
    int idx = blockIdx.x * 256 + threadIdx.x;
    if (idx >= n) return;
    float s = 0.f;
    #pragma unroll
    for (int cc = 0; cc < 8; cc++) s += part[(size_t)cc * n + idx];
    outp[idx] = s;
}

__global__ void lin_out_kernel(const float* __restrict__ Qp, const float* __restrict__ kv,
                               const float* __restrict__ ksum, float* __restrict__ bout,
                               int mode) {
    const int b = blockIdx.z, h = blockIdx.y, t = blockIdx.x;
    __shared__ float sqf[HD];
    __shared__ float red[HD];
    const int tid = threadIdx.x;           // 64
    float qv = Qp[((size_t)(b * LQ + t)) * DM + h * HD + tid];
    if (mode == 0) {
        float x = qv * SCALE;
        sqf[tid] = (x > 0.f) ? (x + 1.f) : __expf(x);
    } else {
        red[tid] = qv * qv;
        __syncthreads();
        #pragma unroll
        for (int o = 32; o > 0; o >>= 1) {
            if (tid < o) red[tid] += red[tid + o];
            __syncthreads();
        }
        float nrm = fmaxf(sqrtf(red[0]), 1e-12f);
        float qn = qv / nrm;
        sqf[tid] = ((qn > 0.f) ? qn : 0.f) + 1e-6f;
    }
    __syncthreads();
    const int bh = b * NH + h;
    const float* kvb = kv + (size_t)bh * HD * HD;
    const float* ksb = ksum + (size_t)bh * HD;
    float accv = 0.f, den = 0.f;
    #pragma unroll 8
    for (int d = 0; d < HD; d++) {
        float qf = sqf[d];
        accv += qf * kvb[d * HD + tid];
        den += qf * ksb[d];
    }
    den = fmaxf(den, 1e-6f);
    bout[((size_t)(b * LQ + t)) * DM + h * HD + tid] = accv / den;
}

// ---------------- probsparse helpers ----------------------------------------
__global__ void psparse_m_kernel(const float* __restrict__ Qp, const float* __restrict__ Kp,
                                 const int* __restrict__ sidx, int nsample,
                                 float* __restrict__ Mout) {
    const int b = blockIdx.z, h = blockIdx.y;
    __shared__ float sks[64 * HD];
    const int tid = threadIdx.x;   // 128
    for (int i = tid; i < nsample * HD; i += 128) {
        int j = i / HD, dd = i % HD;
        sks[i] = Kp[((size_t)(b * LK + sidx[j])) * DM + h * HD + dd];
    }
    __syncthreads();
    const int t = blockIdx.x * 128 + tid;
    float qr[HD];
    const float* qrow = Qp + ((size_t)(b * LQ + t)) * DM + h * HD;
    #pragma unroll
    for (int j = 0; j < HD; j++) qr[j] = qrow[j];
    float mx = -1e30f, sm = 0.f;
    for (int j = 0; j < nsample; j++) {
        float d = 0.f;
        #pragma unroll
        for (int dd = 0; dd < HD; dd++) d += qr[dd] * sks[j * HD + dd];
        mx = fmaxf(mx, d);
        sm += d;
    }
    Mout[((size_t)(b * NH + h)) * LQ + t] = SCALE * (mx - sm / (float)nsample);
}

__global__ void topk_kernel(const float* __restrict__ M, int* __restrict__ topidx) {
    const int bh = blockIdx.x;
    __shared__ float vals[LQ];
    __shared__ float rv[256];
    __shared__ int ri[256];
    const int tid = threadIdx.x;
    vals[tid] = M[(size_t)bh * LQ + tid];
    vals[tid + 256] = M[(size_t)bh * LQ + tid + 256];
    __syncthreads();
    for (int it = 0; it < NTOP; it++) {
        float v1 = vals[tid], v2 = vals[tid + 256];
        float bv; int bi;
        if (v1 >= v2) { bv = v1; bi = tid; } else { bv = v2; bi = tid + 256; }
        rv[tid] = bv; ri[tid] = bi;
        __syncthreads();
        #pragma unroll
        for (int o = 128; o > 0; o >>= 1) {
            if (tid < o) {
                if (rv[tid + o] > rv[tid] ||
                    (rv[tid + o] == rv[tid] && ri[tid + o] < ri[tid])) {
                    rv[tid] = rv[tid + o]; ri[tid] = ri[tid + o];
                }
            }
            __syncthreads();
        }
        if (tid == 0) {
            topidx[bh * NTOP + it] = ri[0];
            vals[ri[0]] = -1e30f;
        }
        __syncthreads();
    }
}

__global__ void vmean_kernel(const float* __restrict__ Vp, float* __restrict__ vmean) {
    const int bh = blockIdx.x;
    const int b = bh / NH, h = bh % NH;
    const int tid = threadIdx.x;            // 256
    const int d = tid % 64, c = tid / 64;   // 4 chunks
    __shared__ float red[4][64];
    float s = 0.f;
    for (int ss = c * (LK / 4); ss < (c + 1) * (LK / 4); ss++)
        s += Vp[((size_t)(b * LK + ss)) * DM + h * HD + d];
    red[c][d] = s;
    __syncthreads();
    if (tid < 64) {
        float r = red[0][tid] + red[1][tid] + red[2][tid] + red[3][tid];
        vmean[bh * HD + tid] = r * (1.0f / LK);
    }
}

__global__ void fill_vmean_kernel(const float* __restrict__ vmean, float* __restrict__ bout) {
    const int idx = blockIdx.x * 256 + threadIdx.x;
    if (idx >= BB * LQ * DM) return;
    const int d = idx % DM;
    const int bt = idx / DM;
    const int b = bt / LQ;
    const int h = d / HD, dh = d % HD;
    bout[idx] = vmean[(b * NH + h) * HD + dh];
}

// ---------------- fused epilogue --------------------------------------------
__global__ __launch_bounds__(256) void epilogue_kernel(const float* __restrict__ dec,
                                                       const float* __restrict__ proj,
                                                       const float* __restrict__ rms_w,
                                                       const float* __restrict__ alphas,
                                                       float* __restrict__ out) {
    const int row = blockIdx.x;
    const int tid = threadIdx.x;
    __shared__ float red[256];

    float a[6], w[6];
    #pragma unroll
    for (int i = 0; i < 6; i++) a[i] = alphas[i];
    float mx = a[0];
    #pragma unroll
    for (int i = 1; i < 6; i++) mx = fmaxf(mx, a[i]);
    float ssum = 0.f;
    #pragma unroll
    for (int i = 0; i < 6; i++) { w[i] = __expf(a[i] - mx); ssum += w[i]; }
    #pragma unroll
    for (int i = 0; i < 6; i++) w[i] /= ssum;

    const size_t base = (size_t)row * DM + tid * 4;
    float4 dv = *(const float4*)(dec + base);
    float4 wv = *(const float4*)(rms_w + (size_t)tid * 4);
    float4 oacc = make_float4(w[0] * dv.x, w[0] * dv.y, w[0] * dv.z, w[0] * dv.w);

    #pragma unroll
    for (int br = 0; br < NBR; br++) {
        float4 pv = *(const float4*)(proj + (size_t)br * MROWS * DM + base);
        float4 x = make_float4(dv.x + pv.x, dv.y + pv.y, dv.z + pv.z, dv.w + pv.w);
        float ss = x.x * x.x + x.y * x.y + x.z * x.z + x.w * x.w;
        red[tid] = ss;
        __syncthreads();
        #pragma unroll
        for (int o = 128; o > 0; o >>= 1) {
            if (tid < o) red[tid] += red[tid + o];
            __syncthreads();
        }
        float rs = rsqrtf(red[0] * (1.f / DM) + 1e-6f);
        __syncthreads();
        float wb = w[br + 1];
        oacc.x += wb * x.x * rs * wv.x;
        oacc.y += wb * x.y * rs * wv.y;
        oacc.z += wb * x.z * rs * wv.z;
        oacc.w += wb * x.w * rs * wv.w;
    }
    *(float4*)(out + base) = oacc;
}

// ---------------- launch ----------------------------------------------------
extern "C" void kernel_launch(void* const* d_in, const int* in_sizes, int n_in,
                              void* d_out, int out_size) {
    const float* dec    = (const float*)d_in[0];
    const float* enc    = (const float*)d_in[1];
    const float* Wq     = (const float*)d_in[2];
    const float* Wk     = (const float*)d_in[3];
    const float* Wv     = (const float*)d_in[4];
    const float* Wo     = (const float*)d_in[5];
    const float* rmsw   = (const float*)d_in[6];
    const float* alphas = (const float*)d_in[7];
    const int*   sidx   = (const int*)d_in[8];
    const int nsample   = in_sizes[8];
    float* out = (float*)d_out;

    float *Qs, *Ks, *Vs, *bo, *pj, *kvp, *ksp, *kv, *ks, *Mv, *vm;
    int* tp;
    cudaGetSymbolAddress((void**)&Qs, g_Q);
    cudaGetSymbolAddress((void**)&Ks, g_K);
    cudaGetSymbolAddress((void**)&Vs, g_V);
    cudaGetSymbolAddress((void**)&bo, g_bout);
    cudaGetSymbolAddress((void**)&pj, g_proj);
    cudaGetSymbolAddress((void**)&kvp, g_kvpart);
    cudaGetSymbolAddress((void**)&ksp, g_kspart);
    cudaGetSymbolAddress((void**)&kv, g_kv);
    cudaGetSymbolAddress((void**)&ks, g_ksum);
    cudaGetSymbolAddress((void**)&Mv, g_M);
    cudaGetSymbolAddress((void**)&tp, g_top);
    cudaGetSymbolAddress((void**)&vm, g_vmean);

    const int FSMEM = 3 * FQ * FP * sizeof(float);   // 52224 B
    cudaFuncSetAttribute(flash_kernel, cudaFuncAttributeMaxDynamicSharedMemorySize, FSMEM);

    const size_t BSTR = (size_t)MROWS * DM;
    const int NKV = BB * NH * HD * HD;
    const int NKS = BB * NH * HD;

    // projections
    sgemm2<<<dim3(DM / GBN, MROWS / GBM), 256>>>(dec, Wq, Qs, MROWS, DM, DM);
    sgemm2<<<dim3(DM / GBN, BB * LK / GBM), 256>>>(enc, Wk, Ks, BB * LK, DM, DM);
    sgemm2<<<dim3(DM / GBN, BB * LK / GBM), 256>>>(enc, Wv, Vs, BB * LK, DM, DM);

    // branch 0: dense SDP
    flash_kernel<<<dim3(LQ / FQ, NH, BB), 256, FSMEM>>>(Qs, Ks, Vs, bo, nullptr, 0);

    // branch 1: linear
    kvchunk_kernel<<<dim3(8, NH, BB), 256>>>(Ks, Vs, kvp, ksp, 0);
    kvreduce_kernel<<<(NKV + 255) / 256, 256>>>(kvp, kv, NKV);
    kvreduce_kernel<<<(NKS + 255) / 256, 256>>>(ksp, ks, NKS);
    lin_out_kernel<<<dim3(LQ, NH, BB), 64>>>(Qs, kv, ks, bo + 1 * BSTR, 0);

    // branch 2: probsparse
    psparse_m_kernel<<<dim3(LQ / 128, NH, BB), 128>>>(Qs, Ks, sidx, nsample, Mv);
    topk_kernel<<<BB * NH, 256>>>(Mv, tp);
    vmean_kernel<<<BB * NH, 256>>>(Vs, vm);
    fill_vmean_kernel<<<(BB * LQ * DM + 255) / 256, 256>>>(vm, bo + 2 * BSTR);
    flash_kernel<<<dim3(1, NH, BB), 256, FSMEM>>>(Qs, Ks, Vs, bo + 2 * BSTR, tp, 2);

    // branch 3: cosine
    kvchunk_kernel<<<dim3(8, NH, BB), 256>>>(Ks, Vs, kvp, ksp, 1);
    kvreduce_kernel<<<(NKV + 255) / 256, 256>>>(kvp, kv, NKV);
    kvreduce_kernel<<<(NKS + 255) / 256, 256>>>(ksp, ks, NKS);
    lin_out_kernel<<<dim3(LQ, NH, BB), 64>>>(Qs, kv, ks, bo + 3 * BSTR, 1);

    // branch 4: local windowed
    flash_kernel<<<dim3(LQ / FQ, NH, BB), 256, FSMEM>>>(Qs, Ks, Vs, bo + 4 * BSTR, nullptr, 1);

    // batched output projection: [5*1024, 1024] @ Wo
    sgemm2<<<dim3(DM / GBN, NBR * MROWS / GBM), 256>>>(bo, Wo, pj, NBR * MROWS, DM, DM);

    // fused epilogue
    epilogue_kernel<<<MROWS, 256>>>(dec, pj, rmsw, alphas, out);
}

// round 4
// speedup vs baseline: 6.4484x; 1.2563x over previous
#include <cuda_runtime.h>
#include <cuda_bf16.h>
#include <math.h>
#include <stdint.h>

#define BB 2
#define LQ 512
#define LK 2048
#define DM 1024
#define NH 16
#define HD 64
#define SCALE 0.125f
#define NTOP 31
#define NBR 5
#define MROWS (BB * LQ)           // 1024

typedef __nv_bfloat16 bf16;

// ---------------- scratch ----------------------------------------------------
__device__ float g_Q[BB * LQ * DM];
__device__ float g_K[BB * LK * DM];
__device__ float g_V[BB * LK * DM];
__device__ float g_bout[NBR * MROWS * DM];
__device__ float g_proj[NBR * MROWS * DM];
__device__ float g_kvpart[8 * BB * NH * HD * HD];
__device__ float g_kspart[8 * BB * NH * HD];
__device__ float g_kv[BB * NH * HD * HD];
__device__ float g_ksum[BB * NH * HD];
__device__ float g_M[BB * NH * LQ];
__device__ int   g_top[BB * NH * NTOP];
__device__ float g_vmean[BB * NH * HD];

// bf16 split buffers
__device__ bf16 g_decH[MROWS * DM],  g_decL[MROWS * DM];
__device__ bf16 g_encH[BB * LK * DM], g_encL[BB * LK * DM];
__device__ bf16 g_boH[NBR * MROWS * DM], g_boL[NBR * MROWS * DM];
__device__ bf16 g_WqH[DM * DM], g_WqL[DM * DM];
__device__ bf16 g_WkH[DM * DM], g_WkL[DM * DM];
__device__ bf16 g_WvH[DM * DM], g_WvL[DM * DM];
__device__ bf16 g_WoH[DM * DM], g_WoL[DM * DM];

// ---------------- split fp32 -> (hi, lo) bf16 --------------------------------
__global__ void split_kernel(const float* __restrict__ x, bf16* __restrict__ hi,
                             bf16* __restrict__ lo, int n) {
    int i = (blockIdx.x * 256 + threadIdx.x) * 4;
    if (i >= n) return;
    float4 v = *(const float4*)(x + i);
    bf16 h0 = __float2bfloat16(v.x), h1 = __float2bfloat16(v.y);
    bf16 h2 = __float2bfloat16(v.z), h3 = __float2bfloat16(v.w);
    bf16 l0 = __float2bfloat16(v.x - __bfloat162float(h0));
    bf16 l1 = __float2bfloat16(v.y - __bfloat162float(h1));
    bf16 l2 = __float2bfloat16(v.z - __bfloat162float(h2));
    bf16 l3 = __float2bfloat16(v.w - __bfloat162float(h3));
    __nv_bfloat162* hp = (__nv_bfloat162*)(hi + i);
    __nv_bfloat162* lp = (__nv_bfloat162*)(lo + i);
    hp[0] = __nv_bfloat162(h0, h1); hp[1] = __nv_bfloat162(h2, h3);
    lp[0] = __nv_bfloat162(l0, l1); lp[1] = __nv_bfloat162(l2, l3);
}

// ---------------- split + transpose weights: out[n][k] = W[k][n] -------------
__global__ void splitT_kernel(const float* __restrict__ W, bf16* __restrict__ hiT,
                              bf16* __restrict__ loT) {
    __shared__ float tile[32][33];
    const int bx = blockIdx.x * 32;   // n base
    const int by = blockIdx.y * 32;   // k base
    const int tx = threadIdx.x, ty = threadIdx.y;   // 32 x 8
    #pragma unroll
    for (int j = 0; j < 4; j++)
        tile[ty + j * 8][tx] = W[(size_t)(by + ty + j * 8) * DM + bx + tx];
    __syncthreads();
    #pragma unroll
    for (int j = 0; j < 4; j++) {
        float v = tile[tx][ty + j * 8];
        bf16 h = __float2bfloat16(v);
        bf16 l = __float2bfloat16(v - __bfloat162float(h));
        size_t o = (size_t)(bx + ty + j * 8) * DM + by + tx;
        hiT[o] = h; loT[o] = l;
    }
}

// ---------------- bf16-split tensor-core GEMM --------------------------------
// C[M,N] = (Ahi+Alo)[M,K] @ (Bhi+Blo)^T where BT stored [N][K]
__device__ __forceinline__ void mma_bf16(float c[4], const uint32_t a[4], const uint32_t b[2]) {
    asm volatile(
        "mma.sync.aligned.m16n8k16.row.col.f32.bf16.bf16.f32 "
        "{%0,%1,%2,%3}, {%4,%5,%6,%7}, {%8,%9}, {%0,%1,%2,%3};"
        : "+f"(c[0]), "+f"(c[1]), "+f"(c[2]), "+f"(c[3])
        : "r"(a[0]), "r"(a[1]), "r"(a[2]), "r"(a[3]), "r"(b[0]), "r"(b[1]));
}

#define SPAD 40   // smem row stride in bf16 (conflict-free for g*20+t word pattern)
__global__ __launch_bounds__(256, 1) void bgemm(const bf16* __restrict__ Ahi,
                                                const bf16* __restrict__ Alo,
                                                const bf16* __restrict__ BhiT,
                                                const bf16* __restrict__ BloT,
                                                float* __restrict__ C,
                                                int M, int N, int K) {
    __shared__ bf16 sAh[128 * SPAD];
    __shared__ bf16 sAl[128 * SPAD];
    __shared__ bf16 sBh[128 * SPAD];
    __shared__ bf16 sBl[128 * SPAD];

    const int bm = blockIdx.y * 128;
    const int bn = blockIdx.x * 128;
    const int tid = threadIdx.x;
    const int wid = tid >> 5, lane = tid & 31;
    const int wm = (wid >> 2) * 64;       // warp m base (0 or 64)
    const int wn = (wid & 3) * 32;        // warp n base
    const int g = lane >> 2, t = lane & 3;

    float acc[4][4][4];
    #pragma unroll
    for (int mi = 0; mi < 4; mi++)
        #pragma unroll
        for (int ni = 0; ni < 4; ni++)
            #pragma unroll
            for (int r = 0; r < 4; r++) acc[mi][ni][r] = 0.f;

    for (int k0 = 0; k0 < K; k0 += 32) {
        // each thread loads 2 uint4 (8 bf16) per array
        uint4 vah[2], val[2], vbh[2], vbl[2];
        int rows[2], kcs[2];
        #pragma unroll
        for (int i = 0; i < 2; i++) {
            int idx = i * 256 + tid;
            rows[i] = idx >> 2;
            kcs[i] = (idx & 3) * 8;
            const size_t ga = (size_t)(bm + rows[i]) * K + k0 + kcs[i];
            const size_t gb = (size_t)(bn + rows[i]) * K + k0 + kcs[i];
            vah[i] = *(const uint4*)(Ahi + ga);
            val[i] = *(const uint4*)(Alo + ga);
            vbh[i] = *(const uint4*)(BhiT + gb);
            vbl[i] = *(const uint4*)(BloT + gb);
        }
        __syncthreads();
        #pragma unroll
        for (int i = 0; i < 2; i++) {
            int so = rows[i] * SPAD + kcs[i];
            *(uint4*)(sAh + so) = vah[i];
            *(uint4*)(sAl + so) = val[i];
            *(uint4*)(sBh + so) = vbh[i];
            *(uint4*)(sBl + so) = vbl[i];
        }
        __syncthreads();

        #pragma unroll
        for (int ks = 0; ks < 32; ks += 16) {
            uint32_t ah[4][4], al[4][4], bh[4][2], bl[4][2];
            #pragma unroll
            for (int mi = 0; mi < 4; mi++) {
                int r0 = wm + mi * 16;
                ah[mi][0] = *(const uint32_t*)(sAh + (r0 + g) * SPAD + ks + 2 * t);
                ah[mi][1] = *(const uint32_t*)(sAh + (r0 + g + 8) * SPAD + ks + 2 * t);
                ah[mi][2] = *(const uint32_t*)(sAh + (r0 + g) * SPAD + ks + 8 + 2 * t);
                ah[mi][3] = *(const uint32_t*)(sAh + (r0 + g + 8) * SPAD + ks + 8 + 2 * t);
                al[mi][0] = *(const uint32_t*)(sAl + (r0 + g) * SPAD + ks + 2 * t);
                al[mi][1] = *(const uint32_t*)(sAl + (r0 + g + 8) * SPAD + ks + 2 * t);
                al[mi][2] = *(const uint32_t*)(sAl + (r0 + g) * SPAD + ks + 8 + 2 * t);
                al[mi][3] = *(const uint32_t*)(sAl + (r0 + g + 8) * SPAD + ks + 8 + 2 * t);
            }
            #pragma unroll
            for (int ni = 0; ni < 4; ni++) {
                int c0 = wn + ni * 8;
                bh[ni][0] = *(const uint32_t*)(sBh + (c0 + g) * SPAD + ks + 2 * t);
                bh[ni][1] = *(const uint32_t*)(sBh + (c0 + g) * SPAD + ks + 8 + 2 * t);
                bl[ni][0] = *(const uint32_t*)(sBl + (c0 + g) * SPAD + ks + 2 * t);
                bl[ni][1] = *(const uint32_t*)(sBl + (c0 + g) * SPAD + ks + 8 + 2 * t);
            }
            #pragma unroll
            for (int mi = 0; mi < 4; mi++)
                #pragma unroll
                for (int ni = 0; ni < 4; ni++) {
                    mma_bf16(acc[mi][ni], ah[mi], bh[ni]);
                    mma_bf16(acc[mi][ni], ah[mi], bl[ni]);
                    mma_bf16(acc[mi][ni], al[mi], bh[ni]);
                }
        }
        __syncthreads();
    }

    #pragma unroll
    for (int mi = 0; mi < 4; mi++) {
        #pragma unroll
        for (int ni = 0; ni < 4; ni++) {
            int row = bm + wm + mi * 16 + g;
            int col = bn + wn + ni * 8 + 2 * t;
            *(float2*)(C + (size_t)row * N + col) =
                make_float2(acc[mi][ni][0], acc[mi][ni][1]);
            *(float2*)(C + (size_t)(row + 8) * N + col) =
                make_float2(acc[mi][ni][2], acc[mi][ni][3]);
        }
    }
}

// ---------------- flash attention (unchanged) --------------------------------
#define FQ 64
#define FS 64
#define FP 68
__global__ __launch_bounds__(256) void flash_kernel(const float* __restrict__ Qp,
                                                    const float* __restrict__ Kp,
                                                    const float* __restrict__ Vp,
                                                    float* __restrict__ bout,
                                                    const int* __restrict__ row_map,
                                                    int mode) {
    extern __shared__ float fsm[];
    float* Qs  = fsm;
    float* KVs = fsm + FQ * FP;
    float* Ps  = fsm + 2 * FQ * FP;

    const int b = blockIdx.z, h = blockIdx.y;
    const int qbase = blockIdx.x * FQ;
    const int tid = threadIdx.x;
    const int ty = tid / 16, tx = tid % 16;

    #pragma unroll
    for (int r = 0; r < 4; r++) {
        int idx = r * 256 + tid;
        int q = idx / 16, dg = (idx % 16) * 4;
        int t; bool valid = true;
        if (mode == 2) {
            if (q < NTOP) t = row_map[(b * NH + h) * NTOP + q];
            else { t = 0; valid = false; }
        } else t = qbase + q;
        float4 v = valid ? *(const float4*)(Qp + ((size_t)(b * LQ + t)) * DM + h * HD + dg)
                         : make_float4(0.f, 0.f, 0.f, 0.f);
        *(float4*)&Qs[q * FP + dg] = v;
    }
    __syncthreads();

    float m_i[4], l_i[4], acc[4][4];
    #pragma unroll
    for (int i = 0; i < 4; i++) {
        m_i[i] = -1e30f; l_i[i] = 0.f;
        #pragma unroll
        for (int j = 0; j < 4; j++) acc[i][j] = 0.f;
    }

    int st_lo = 0, st_hi = LK / FS - 1;
    if (mode == 1) {
        int lo = max(0, 4 * qbase - 256);
        int hi = min(LK - 1, 4 * (qbase + FQ - 1) + 256);
        st_lo = lo / FS; st_hi = hi / FS;
    }

    for (int st = st_lo; st <= st_hi; st++) {
        const int s0 = st * FS;
        #pragma unroll
        for (int r = 0; r < 4; r++) {
            int idx = r * 256 + tid;
            int s = idx / 16, dg = (idx % 16) * 4;
            *(float4*)&KVs[s * FP + dg] =
                *(const float4*)(Kp + ((size_t)(b * LK + s0 + s)) * DM + h * HD + dg);
        }
        __syncthreads();

        float sc[4][4];
        #pragma unroll
        for (int i = 0; i < 4; i++)
            #pragma unroll
            for (int j = 0; j < 4; j++) sc[i][j] = 0.f;
        #pragma unroll
        for (int d4 = 0; d4 < 16; d4++) {
            float4 qv[4], kv[4];
            #pragma unroll
            for (int i = 0; i < 4; i++) qv[i] = *(float4*)&Qs[(ty * 4 + i) * FP + d4 * 4];
            #pragma unroll
            for (int j = 0; j < 4; j++) kv[j] = *(float4*)&KVs[(tx + 16 * j) * FP + d4 * 4];
            #pragma unroll
            for (int i = 0; i < 4; i++)
                #pragma unroll
                for (int j = 0; j < 4; j++)
                    sc[i][j] += qv[i].x * kv[j].x + qv[i].y * kv[j].y +
                                qv[i].z * kv[j].z + qv[i].w * kv[j].w;
        }
        #pragma unroll
        for (int i = 0; i < 4; i++)
            #pragma unroll
            for (int j = 0; j < 4; j++) sc[i][j] *= SCALE;

        if (mode == 1) {
            #pragma unroll
            for (int i = 0; i < 4; i++) {
                int t = qbase + ty * 4 + i;
                int center = min(4 * t, LK - 1);
                int lo = max(center - 256, 0);
                int hi = min(center + 256, LK - 1);
                #pragma unroll
                for (int j = 0; j < 4; j++) {
                    int s = s0 + tx + 16 * j;
                    if (s < lo || s > hi) sc[i][j] = -1e30f;
                }
            }
        }

        #pragma unroll
        for (int i = 0; i < 4; i++) {
            float rmax = fmaxf(fmaxf(sc[i][0], sc[i][1]), fmaxf(sc[i][2], sc[i][3]));
            #pragma unroll
            for (int off = 1; off < 16; off <<= 1)
                rmax = fmaxf(rmax, __shfl_xor_sync(0xffffffffu, rmax, off, 16));
            float nm = fmaxf(m_i[i], rmax);
            float corr = __expf(m_i[i] - nm);
            float rsum = 0.f;
            float p[4];
            #pragma unroll
            for (int j = 0; j < 4; j++) {
                p[j] = (sc[i][j] < -5e29f) ? 0.f : __expf(sc[i][j] - nm);
                rsum += p[j];
            }
            #pragma unroll
            for (int off = 1; off < 16; off <<= 1)
                rsum += __shfl_xor_sync(0xffffffffu, rsum, off, 16);
            l_i[i] = l_i[i] * corr + rsum;
            #pragma unroll
            for (int j = 0; j < 4; j++) acc[i][j] *= corr;
            m_i[i] = nm;
            #pragma unroll
            for (int j = 0; j < 4; j++)
                Ps[(ty * 4 + i) * FP + tx + 16 * j] = p[j];
        }
        __syncthreads();

        #pragma unroll
        for (int r = 0; r < 4; r++) {
            int idx = r * 256 + tid;
            int s = idx / 16, dg = (idx % 16) * 4;
            *(float4*)&KVs[s * FP + dg] =
                *(const float4*)(Vp + ((size_t)(b * LK + s0 + s)) * DM + h * HD + dg);
        }
        __syncthreads();

        #pragma unroll 8
        for (int s = 0; s < FS; s++) {
            float4 vv = *(float4*)&KVs[s * FP + tx * 4];
            #pragma unroll
            for (int i = 0; i < 4; i++) {
                float pi = Ps[(ty * 4 + i) * FP + s];
                acc[i][0] += pi * vv.x; acc[i][1] += pi * vv.y;
                acc[i][2] += pi * vv.z; acc[i][3] += pi * vv.w;
            }
        }
        __syncthreads();
    }

    #pragma unroll
    for (int i = 0; i < 4; i++) {
        int q = ty * 4 + i;
        int t;
        if (mode == 2) {
            if (q >= NTOP) continue;
            t = row_map[(b * NH + h) * NTOP + q];
        } else t = qbase + q;
        float inv = 1.f / l_i[i];
        float4 o = make_float4(acc[i][0] * inv, acc[i][1] * inv,
                               acc[i][2] * inv, acc[i][3] * inv);
        *(float4*)(bout + ((size_t)(b * LQ + t)) * DM + h * HD + tx * 4) = o;
    }
}

// ---------------- linear/cosine KV aggregation -------------------------------
__global__ void kvchunk_kernel(const float* __restrict__ Kp, const float* __restrict__ Vp,
                               float* __restrict__ kvpart, float* __restrict__ kspart,
                               int mode) {
    const int c = blockIdx.x, h = blockIdx.y, b = blockIdx.z;
    __shared__ float sk[32][HD];
    __shared__ float sv[32][HD];
    __shared__ float snorm[32];
    const int tid = threadIdx.x;
    const int dmy = tid / 4, vg = tid % 4;
    float acc[16];
    #pragma unroll
    for (int j = 0; j < 16; j++) acc[j] = 0.f;
    float ksacc = 0.f;
    const int sbeg = c * (LK / 8), send = sbeg + LK / 8;

    for (int s0 = sbeg; s0 < send; s0 += 32) {
        for (int i = tid; i < 32 * HD; i += 256) {
            int ss = i / HD, dd = i % HD;
            size_t base = ((size_t)(b * LK + s0 + ss)) * DM + h * HD + dd;
            sk[ss][dd] = Kp[base];
            sv[ss][dd] = Vp[base];
        }
        __syncthreads();
        if (mode == 1 && tid < 32) {
            float n = 0.f;
            #pragma unroll
            for (int j = 0; j < HD; j++) n += sk[tid][j] * sk[tid][j];
            snorm[tid] = fmaxf(sqrtf(n), 1e-12f);
        }
        __syncthreads();
        #pragma unroll 4
        for (int ss = 0; ss < 32; ss++) {
            float kval = sk[ss][dmy];
            float kf;
            if (mode == 0) kf = (kval > 0.f) ? (kval + 1.f) : __expf(kval);
            else {
                float kn = kval / snorm[ss];
                kf = ((kn > 0.f) ? kn : 0.f) + 1e-6f;
            }
            if (vg == 0) ksacc += kf;
            #pragma unroll
            for (int j = 0; j < 16; j++) acc[j] += kf * sv[ss][vg * 16 + j];
        }
        __syncthreads();
    }
    const int bh = b * NH + h;
    const int NKV = BB * NH * HD * HD;
    #pragma unroll
    for (int j = 0; j < 16; j++)
        kvpart[(size_t)c * NKV + ((size_t)bh * HD + dmy) * HD + vg * 16 + j] = acc[j];
    if (vg == 0) kspart[c * (BB * NH * HD) + bh * HD + dmy] = ksacc;
}

__global__ void kvreduce_kernel(const float* __restrict__ part, float* __restrict__ outp, int n) {
    int idx = blockIdx.x * 256 + threadIdx.x;
    if (idx >= n) return;
    float s = 0.f;
    #pragma unroll
    for (int cc = 0; cc < 8; cc++) s += part[(size_t)cc * n + idx];
    outp[idx] = s;
}

__global__ void lin_out_kernel(const float* __restrict__ Qp, const float* __restrict__ kv,
                               const float* __restrict__ ksum, float* __restrict__ bout,
                               int mode) {
    const int b = blockIdx.z, h = blockIdx.y, t = blockIdx.x;
    __shared__ float sqf[HD];
    __shared__ float red[HD];
    const int tid = threadIdx.x;           // 64
    float qv = Qp[((size_t)(b * LQ + t)) * DM + h * HD + tid];
    if (mode == 0) {
        float x = qv * SCALE;
        sqf[tid] = (x > 0.f) ? (x + 1.f) : __expf(x);
    } else {
        red[tid] = qv * qv;
        __syncthreads();
        #pragma unroll
        for (int o = 32; o > 0; o >>= 1) {
            if (tid < o) red[tid] += red[tid + o];
            __syncthreads();
        }
        float nrm = fmaxf(sqrtf(red[0]), 1e-12f);
        float qn = qv / nrm;
        sqf[tid] = ((qn > 0.f) ? qn : 0.f) + 1e-6f;
    }
    __syncthreads();
    const int bh = b * NH + h;
    const float* kvb = kv + (size_t)bh * HD * HD;
    const float* ksb = ksum + (size_t)bh * HD;
    float accv = 0.f, den = 0.f;
    #pragma unroll 8
    for (int d = 0; d < HD; d++) {
        float qf = sqf[d];
        accv += qf * kvb[d * HD + tid];
        den += qf * ksb[d];
    }
    den = fmaxf(den, 1e-6f);
    bout[((size_t)(b * LQ + t)) * DM + h * HD + tid] = accv / den;
}

// ---------------- probsparse helpers -----------------------------------------
__global__ void psparse_m_kernel(const float* __restrict__ Qp, const float* __restrict__ Kp,
                                 const int* __restrict__ sidx, int nsample,
                                 float* __restrict__ Mout) {
    const int b = blockIdx.z, h = blockIdx.y;
    __shared__ float sks[64 * HD];
    const int tid = threadIdx.x;   // 128
    for (int i = tid; i < nsample * HD; i += 128) {
        int j = i / HD, dd = i % HD;
        sks[i] = Kp[((size_t)(b * LK + sidx[j])) * DM + h * HD + dd];
    }
    __syncthreads();
    const int t = blockIdx.x * 128 + tid;
    float qr[HD];
    const float* qrow = Qp + ((size_t)(b * LQ + t)) * DM + h * HD;
    #pragma unroll
    for (int j = 0; j < HD; j++) qr[j] = qrow[j];
    float mx = -1e30f, sm = 0.f;
    for (int j = 0; j < nsample; j++) {
        float d = 0.f;
        #pragma unroll
        for (int dd = 0; dd < HD; dd++) d += qr[dd] * sks[j * HD + dd];
        mx = fmaxf(mx, d);
        sm += d;
    }
    Mout[((size_t)(b * NH + h)) * LQ + t] = SCALE * (mx - sm / (float)nsample);
}

__global__ void topk_kernel(const float* __restrict__ M, int* __restrict__ topidx) {
    const int bh = blockIdx.x;
    __shared__ float vals[LQ];
    __shared__ float rv[256];
    __shared__ int ri[256];
    const int tid = threadIdx.x;
    vals[tid] = M[(size_t)bh * LQ + tid];
    vals[tid + 256] = M[(size_t)bh * LQ + tid + 256];
    __syncthreads();
    for (int it = 0; it < NTOP; it++) {
        float v1 = vals[tid], v2 = vals[tid + 256];
        float bv; int bi;
        if (v1 >= v2) { bv = v1; bi = tid; } else { bv = v2; bi = tid + 256; }
        rv[tid] = bv; ri[tid] = bi;
        __syncthreads();
        #pragma unroll
        for (int o = 128; o > 0; o >>= 1) {
            if (tid < o) {
                if (rv[tid + o] > rv[tid] ||
                    (rv[tid + o] == rv[tid] && ri[tid + o] < ri[tid])) {
                    rv[tid] = rv[tid + o]; ri[tid] = ri[tid + o];
                }
            }
            __syncthreads();
        }
        if (tid == 0) {
            topidx[bh * NTOP + it] = ri[0];
            vals[ri[0]] = -1e30f;
        }
        __syncthreads();
    }
}

__global__ void vmean_kernel(const float* __restrict__ Vp, float* __restrict__ vmean) {
    const int bh = blockIdx.x;
    const int b = bh / NH, h = bh % NH;
    const int tid = threadIdx.x;            // 256
    const int d = tid % 64, c = tid / 64;
    __shared__ float red[4][64];
    float s = 0.f;
    for (int ss = c * (LK / 4); ss < (c + 1) * (LK / 4); ss++)
        s += Vp[((size_t)(b * LK + ss)) * DM + h * HD + d];
    red[c][d] = s;
    __syncthreads();
    if (tid < 64) {
        float r = red[0][tid] + red[1][tid] + red[2][tid] + red[3][tid];
        vmean[bh * HD + tid] = r * (1.0f / LK);
    }
}

__global__ void fill_vmean_kernel(const float* __restrict__ vmean, float* __restrict__ bout) {
    const int idx = blockIdx.x * 256 + threadIdx.x;
    if (idx >= BB * LQ * DM) return;
    const int d = idx % DM;
    const int bt = idx / DM;
    const int b = bt / LQ;
    const int h = d / HD, dh = d % HD;
    bout[idx] = vmean[(b * NH + h) * HD + dh];
}

// ---------------- fused epilogue ----------------------------------------------
__global__ __launch_bounds__(256) void epilogue_kernel(const float* __restrict__ dec,
                                                       const float* __restrict__ proj,
                                                       const float* __restrict__ rms_w,
                                                       const float* __restrict__ alphas,
                                                       float* __restrict__ out) {
    const int row = blockIdx.x;
    const int tid = threadIdx.x;
    __shared__ float red[256];

    float a[6], w[6];
    #pragma unroll
    for (int i = 0; i < 6; i++) a[i] = alphas[i];
    float mx = a[0];
    #pragma unroll
    for (int i = 1; i < 6; i++) mx = fmaxf(mx, a[i]);
    float ssum = 0.f;
    #pragma unroll
    for (int i = 0; i < 6; i++) { w[i] = __expf(a[i] - mx); ssum += w[i]; }
    #pragma unroll
    for (int i = 0; i < 6; i++) w[i] /= ssum;

    const size_t base = (size_t)row * DM + tid * 4;
    float4 dv = *(const float4*)(dec + base);
    float4 wv = *(const float4*)(rms_w + (size_t)tid * 4);
    float4 oacc = make_float4(w[0] * dv.x, w[0] * dv.y, w[0] * dv.z, w[0] * dv.w);

    #pragma unroll
    for (int br = 0; br < NBR; br++) {
        float4 pv = *(const float4*)(proj + (size_t)br * MROWS * DM + base);
        float4 x = make_float4(dv.x + pv.x, dv.y + pv.y, dv.z + pv.z, dv.w + pv.w);
        float ss = x.x * x.x + x.y * x.y + x.z * x.z + x.w * x.w;
        red[tid] = ss;
        __syncthreads();
        #pragma unroll
        for (int o = 128; o > 0; o >>= 1) {
            if (tid < o) red[tid] += red[tid + o];
            __syncthreads();
        }
        float rs = rsqrtf(red[0] * (1.f / DM) + 1e-6f);
        __syncthreads();
        float wb = w[br + 1];
        oacc.x += wb * x.x * rs * wv.x;
        oacc.y += wb * x.y * rs * wv.y;
        oacc.z += wb * x.z * rs * wv.z;
        oacc.w += wb * x.w * rs * wv.w;
    }
    *(float4*)(out + base) = oacc;
}

// ---------------- launch -------------------------------------------------------
extern "C" void kernel_launch(void* const* d_in, const int* in_sizes, int n_in,
                              void* d_out, int out_size) {
    const float* dec    = (const float*)d_in[0];
    const float* enc    = (const float*)d_in[1];
    const float* Wq     = (const float*)d_in[2];
    const float* Wk     = (const float*)d_in[3];
    const float* Wv     = (const float*)d_in[4];
    const float* Wo     = (const float*)d_in[5];
    const float* rmsw   = (const float*)d_in[6];
    const float* alphas = (const float*)d_in[7];
    const int*   sidx   = (const int*)d_in[8];
    const int nsample   = in_sizes[8];
    float* out = (float*)d_out;

    float *Qs, *Ks, *Vs, *bo, *pj, *kvp, *ksp, *kv, *ks, *Mv, *vm;
    int* tp;
    bf16 *decH, *decL, *encH, *encL, *boH, *boL;
    bf16 *WqH, *WqL, *WkH, *WkL, *WvH, *WvL, *WoH, *WoL;
    cudaGetSymbolAddress((void**)&Qs, g_Q);
    cudaGetSymbolAddress((void**)&Ks, g_K);
    cudaGetSymbolAddress((void**)&Vs, g_V);
    cudaGetSymbolAddress((void**)&bo, g_bout);
    cudaGetSymbolAddress((void**)&pj, g_proj);
    cudaGetSymbolAddress((void**)&kvp, g_kvpart);
    cudaGetSymbolAddress((void**)&ksp, g_kspart);
    cudaGetSymbolAddress((void**)&kv, g_kv);
    cudaGetSymbolAddress((void**)&ks, g_ksum);
    cudaGetSymbolAddress((void**)&Mv, g_M);
    cudaGetSymbolAddress((void**)&tp, g_top);
    cudaGetSymbolAddress((void**)&vm, g_vmean);
    cudaGetSymbolAddress((void**)&decH, g_decH);
    cudaGetSymbolAddress((void**)&decL, g_decL);
    cudaGetSymbolAddress((void**)&encH, g_encH);
    cudaGetSymbolAddress((void**)&encL, g_encL);
    cudaGetSymbolAddress((void**)&boH, g_boH);
    cudaGetSymbolAddress((void**)&boL, g_boL);
    cudaGetSymbolAddress((void**)&WqH, g_WqH);
    cudaGetSymbolAddress((void**)&WqL, g_WqL);
    cudaGetSymbolAddress((void**)&WkH, g_WkH);
    cudaGetSymbolAddress((void**)&WkL, g_WkL);
    cudaGetSymbolAddress((void**)&WvH, g_WvH);
    cudaGetSymbolAddress((void**)&WvL, g_WvL);
    cudaGetSymbolAddress((void**)&WoH, g_WoH);
    cudaGetSymbolAddress((void**)&WoL, g_WoL);

    const int FSMEM = 3 * FQ * FP * sizeof(float);
    cudaFuncSetAttribute(flash_kernel, cudaFuncAttributeMaxDynamicSharedMemorySize, FSMEM);

    const size_t BSTR = (size_t)MROWS * DM;
    const int NKV = BB * NH * HD * HD;
    const int NKS = BB * NH * HD;

    dim3 tgrid(DM / 32, DM / 32);
    dim3 tblk(32, 8);

    // splits: weights (transposed) + activations
    splitT_kernel<<<tgrid, tblk>>>(Wq, WqH, WqL);
    splitT_kernel<<<tgrid, tblk>>>(Wk, WkH, WkL);
    splitT_kernel<<<tgrid, tblk>>>(Wv, WvH, WvL);
    splitT_kernel<<<tgrid, tblk>>>(Wo, WoH, WoL);
    split_kernel<<<(MROWS * DM / 4 + 255) / 256, 256>>>(dec, decH, decL, MROWS * DM);
    split_kernel<<<(BB * LK * DM / 4 + 255) / 256, 256>>>(enc, encH, encL, BB * LK * DM);

    // projections via tensor-core split GEMM
    bgemm<<<dim3(DM / 128, MROWS / 128), 256>>>(decH, decL, WqH, WqL, Qs, MROWS, DM, DM);
    bgemm<<<dim3(DM / 128, BB * LK / 128), 256>>>(encH, encL, WkH, WkL, Ks, BB * LK, DM, DM);
    bgemm<<<dim3(DM / 128, BB * LK / 128), 256>>>(encH, encL, WvH, WvL, Vs, BB * LK, DM, DM);

    // branch 0: dense SDP
    flash_kernel<<<dim3(LQ / FQ, NH, BB), 256, FSMEM>>>(Qs, Ks, Vs, bo, nullptr, 0);

    // branch 1: linear
    kvchunk_kernel<<<dim3(8, NH, BB), 256>>>(Ks, Vs, kvp, ksp, 0);
    kvreduce_kernel<<<(NKV + 255) / 256, 256>>>(kvp, kv, NKV);
    kvreduce_kernel<<<(NKS + 255) / 256, 256>>>(ksp, ks, NKS);
    lin_out_kernel<<<dim3(LQ, NH, BB), 64>>>(Qs, kv, ks, bo + 1 * BSTR, 0);

    // branch 2: probsparse
    psparse_m_kernel<<<dim3(LQ / 128, NH, BB), 128>>>(Qs, Ks, sidx, nsample, Mv);
    topk_kernel<<<BB * NH, 256>>>(Mv, tp);
    vmean_kernel<<<BB * NH, 256>>>(Vs, vm);
    fill_vmean_kernel<<<(BB * LQ * DM + 255) / 256, 256>>>(vm, bo + 2 * BSTR);
    flash_kernel<<<dim3(1, NH, BB), 256, FSMEM>>>(Qs, Ks, Vs, bo + 2 * BSTR, tp, 2);

    // branch 3: cosine
    kvchunk_kernel<<<dim3(8, NH, BB), 256>>>(Ks, Vs, kvp, ksp, 1);
    kvreduce_kernel<<<(NKV + 255) / 256, 256>>>(kvp, kv, NKV);
    kvreduce_kernel<<<(NKS + 255) / 256, 256>>>(ksp, ks, NKS);
    lin_out_kernel<<<dim3(LQ, NH, BB), 64>>>(Qs, kv, ks, bo + 3 * BSTR, 1);

    // branch 4: local windowed
    flash_kernel<<<dim3(LQ / FQ, NH, BB), 256, FSMEM>>>(Qs, Ks, Vs, bo + 4 * BSTR, nullptr, 1);

    // split branch outputs, then batched output projection
    split_kernel<<<(NBR * MROWS * DM / 4 + 255) / 256, 256>>>(bo, boH, boL, NBR * MROWS * DM);
    bgemm<<<dim3(DM / 128, NBR * MROWS / 128), 256>>>(boH, boL, WoH, WoL, pj, NBR * MROWS, DM, DM);

    // fused epilogue
    epilogue_kernel<<<MROWS, 256>>>(dec, pj, rmsw, alphas, out);
}

// round 6
// speedup vs baseline: 7.6739x; 1.1901x over previous
#include <cuda_runtime.h>
#include <cuda_bf16.h>
#include <math.h>
#include <stdint.h>

#define BB 2
#define LQ 512
#define LK 2048
#define DM 1024
#define NH 16
#define HD 64
#define SCALE 0.125f
#define NTOP 31
#define NBR 5
#define MROWS (BB * LQ)

typedef __nv_bfloat16 bf16;

// ---------------- scratch ----------------------------------------------------
__device__ float g_Q[BB * LQ * DM];
__device__ float g_K[BB * LK * DM];
__device__ float g_V[BB * LK * DM];
__device__ float g_bout[NBR * MROWS * DM];
__device__ float g_proj[NBR * MROWS * DM];
__device__ float g_kvpart[8 * BB * NH * HD * HD];
__device__ float g_kspart[8 * BB * NH * HD];
__device__ float g_kv[BB * NH * HD * HD];
__device__ float g_ksum[BB * NH * HD];
__device__ float g_M[BB * NH * LQ];
__device__ int   g_top[BB * NH * NTOP];
__device__ float g_vmean[BB * NH * HD];

// bf16 split buffers
__device__ bf16 g_decH[MROWS * DM],  g_decL[MROWS * DM];
__device__ bf16 g_encH[BB * LK * DM], g_encL[BB * LK * DM];
__device__ bf16 g_boH[NBR * MROWS * DM], g_boL[NBR * MROWS * DM];
__device__ bf16 g_WqH[DM * DM], g_WqL[DM * DM];
__device__ bf16 g_WkH[DM * DM], g_WkL[DM * DM];
__device__ bf16 g_WvH[DM * DM], g_WvL[DM * DM];
__device__ bf16 g_WoH[DM * DM], g_WoL[DM * DM];
// flash inputs
__device__ bf16 g_QH[MROWS * DM],  g_QL[MROWS * DM];
__device__ bf16 g_KH[BB * LK * DM], g_KL[BB * LK * DM];
__device__ bf16 g_VTH[BB * NH * HD * LK], g_VTL[BB * NH * HD * LK];

// ---------------- split fp32 -> (hi, lo) bf16 --------------------------------
__global__ void split_kernel(const float* __restrict__ x, bf16* __restrict__ hi,
                             bf16* __restrict__ lo, int n) {
    int i = (blockIdx.x * 256 + threadIdx.x) * 4;
    if (i >= n) return;
    float4 v = *(const float4*)(x + i);
    bf16 h0 = __float2bfloat16(v.x), h1 = __float2bfloat16(v.y);
    bf16 h2 = __float2bfloat16(v.z), h3 = __float2bfloat16(v.w);
    bf16 l0 = __float2bfloat16(v.x - __bfloat162float(h0));
    bf16 l1 = __float2bfloat16(v.y - __bfloat162float(h1));
    bf16 l2 = __float2bfloat16(v.z - __bfloat162float(h2));
    bf16 l3 = __float2bfloat16(v.w - __bfloat162float(h3));
    __nv_bfloat162* hp = (__nv_bfloat162*)(hi + i);
    __nv_bfloat162* lp = (__nv_bfloat162*)(lo + i);
    hp[0] = __nv_bfloat162(h0, h1); hp[1] = __nv_bfloat162(h2, h3);
    lp[0] = __nv_bfloat162(l0, l1); lp[1] = __nv_bfloat162(l2, l3);
}

// ---------------- split + transpose weights: out[n][k] = W[k][n] -------------
__global__ void splitT_kernel(const float* __restrict__ W, bf16* __restrict__ hiT,
                              bf16* __restrict__ loT) {
    __shared__ float tile[32][33];
    const int bx = blockIdx.x * 32;
    const int by = blockIdx.y * 32;
    const int tx = threadIdx.x, ty = threadIdx.y;
    #pragma unroll
    for (int j = 0; j < 4; j++)
        tile[ty + j * 8][tx] = W[(size_t)(by + ty + j * 8) * DM + bx + tx];
    __syncthreads();
    #pragma unroll
    for (int j = 0; j < 4; j++) {
        float v = tile[tx][ty + j * 8];
        bf16 h = __float2bfloat16(v);
        bf16 l = __float2bfloat16(v - __bfloat162float(h));
        size_t o = (size_t)(bx + ty + j * 8) * DM + by + tx;
        hiT[o] = h; loT[o] = l;
    }
}

// ---------------- transpose-split V: VT[(b,h,d)][s] --------------------------
__global__ void vtsplit_kernel(const float* __restrict__ V, bf16* __restrict__ VTh,
                               bf16* __restrict__ VTl) {
    __shared__ float tile[32][33];
    const int b = blockIdx.z;
    const int h = blockIdx.y >> 1;
    const int d0 = (blockIdx.y & 1) * 32;
    const int s0 = blockIdx.x * 32;
    const int tx = threadIdx.x, ty = threadIdx.y;   // 32 x 8
    #pragma unroll
    for (int j = 0; j < 4; j++)
        tile[ty + j * 8][tx] = V[(size_t)(b * LK + s0 + ty + j * 8) * DM + h * HD + d0 + tx];
    __syncthreads();
    #pragma unroll
    for (int j = 0; j < 4; j++) {
        float v = tile[tx][ty + j * 8];
        bf16 hh = __float2bfloat16(v);
        bf16 ll = __float2bfloat16(v - __bfloat162float(hh));
        size_t o = ((size_t)((b * NH + h) * HD + d0 + ty + j * 8)) * LK + s0 + tx;
        VTh[o] = hh; VTl[o] = ll;
    }
}

// ---------------- mma helper --------------------------------------------------
__device__ __forceinline__ void mma_bf16(float c[4], const uint32_t a[4], const uint32_t b[2]) {
    asm volatile(
        "mma.sync.aligned.m16n8k16.row.col.f32.bf16.bf16.f32 "
        "{%0,%1,%2,%3}, {%4,%5,%6,%7}, {%8,%9}, {%0,%1,%2,%3};"
        : "+f"(c[0]), "+f"(c[1]), "+f"(c[2]), "+f"(c[3])
        : "r"(a[0]), "r"(a[1]), "r"(a[2]), "r"(a[3]), "r"(b[0]), "r"(b[1]));
}

__device__ __forceinline__ void split2(float p0, float p1, uint32_t& hi, uint32_t& lo) {
    bf16 h0 = __float2bfloat16(p0), h1 = __float2bfloat16(p1);
    bf16 l0 = __float2bfloat16(p0 - __bfloat162float(h0));
    bf16 l1 = __float2bfloat16(p1 - __bfloat162float(h1));
    __nv_bfloat162 hv(h0, h1), lv(l0, l1);
    hi = *(uint32_t*)&hv; lo = *(uint32_t*)&lv;
}

// ---------------- bf16-split tensor-core GEMM --------------------------------
#define SPAD 40
__global__ __launch_bounds__(256, 1) void bgemm(const bf16* __restrict__ Ahi,
                                                const bf16* __restrict__ Alo,
                                                const bf16* __restrict__ BhiT,
                                                const bf16* __restrict__ BloT,
                                                float* __restrict__ C,
                                                int M, int N, int K) {
    __shared__ bf16 sAh[128 * SPAD];
    __shared__ bf16 sAl[128 * SPAD];
    __shared__ bf16 sBh[128 * SPAD];
    __shared__ bf16 sBl[128 * SPAD];

    const int bm = blockIdx.y * 128;
    const int bn = blockIdx.x * 128;
    const int tid = threadIdx.x;
    const int wid = tid >> 5, lane = tid & 31;
    const int wm = (wid >> 2) * 64;
    const int wn = (wid & 3) * 32;
    const int g = lane >> 2, t = lane & 3;

    float acc[4][4][4];
    #pragma unroll
    for (int mi = 0; mi < 4; mi++)
        #pragma unroll
        for (int ni = 0; ni < 4; ni++)
            #pragma unroll
            for (int r = 0; r < 4; r++) acc[mi][ni][r] = 0.f;

    for (int k0 = 0; k0 < K; k0 += 32) {
        uint4 vah[2], val[2], vbh[2], vbl[2];
        int rows[2], kcs[2];
        #pragma unroll
        for (int i = 0; i < 2; i++) {
            int idx = i * 256 + tid;
            rows[i] = idx >> 2;
            kcs[i] = (idx & 3) * 8;
            const size_t ga = (size_t)(bm + rows[i]) * K + k0 + kcs[i];
            const size_t gb = (size_t)(bn + rows[i]) * K + k0 + kcs[i];
            vah[i] = *(const uint4*)(Ahi + ga);
            val[i] = *(const uint4*)(Alo + ga);
            vbh[i] = *(const uint4*)(BhiT + gb);
            vbl[i] = *(const uint4*)(BloT + gb);
        }
        __syncthreads();
        #pragma unroll
        for (int i = 0; i < 2; i++) {
            int so = rows[i] * SPAD + kcs[i];
            *(uint4*)(sAh + so) = vah[i];
            *(uint4*)(sAl + so) = val[i];
            *(uint4*)(sBh + so) = vbh[i];
            *(uint4*)(sBl + so) = vbl[i];
        }
        __syncthreads();

        #pragma unroll
        for (int ks = 0; ks < 32; ks += 16) {
            uint32_t ah[4][4], al[4][4], bh[4][2], bl[4][2];
            #pragma unroll
            for (int mi = 0; mi < 4; mi++) {
                int r0 = wm + mi * 16;
                ah[mi][0] = *(const uint32_t*)(sAh + (r0 + g) * SPAD + ks + 2 * t);
                ah[mi][1] = *(const uint32_t*)(sAh + (r0 + g + 8) * SPAD + ks + 2 * t);
                ah[mi][2] = *(const uint32_t*)(sAh + (r0 + g) * SPAD + ks + 8 + 2 * t);
                ah[mi][3] = *(const uint32_t*)(sAh + (r0 + g + 8) * SPAD + ks + 8 + 2 * t);
                al[mi][0] = *(const uint32_t*)(sAl + (r0 + g) * SPAD + ks + 2 * t);
                al[mi][1] = *(const uint32_t*)(sAl + (r0 + g + 8) * SPAD + ks + 2 * t);
                al[mi][2] = *(const uint32_t*)(sAl + (r0 + g) * SPAD + ks + 8 + 2 * t);
                al[mi][3] = *(const uint32_t*)(sAl + (r0 + g + 8) * SPAD + ks + 8 + 2 * t);
            }
            #pragma unroll
            for (int ni = 0; ni < 4; ni++) {
                int c0 = wn + ni * 8;
                bh[ni][0] = *(const uint32_t*)(sBh + (c0 + g) * SPAD + ks + 2 * t);
                bh[ni][1] = *(const uint32_t*)(sBh + (c0 + g) * SPAD + ks + 8 + 2 * t);
                bl[ni][0] = *(const uint32_t*)(sBl + (c0 + g) * SPAD + ks + 2 * t);
                bl[ni][1] = *(const uint32_t*)(sBl + (c0 + g) * SPAD + ks + 8 + 2 * t);
            }
            #pragma unroll
            for (int mi = 0; mi < 4; mi++)
                #pragma unroll
                for (int ni = 0; ni < 4; ni++) {
                    mma_bf16(acc[mi][ni], ah[mi], bh[ni]);
                    mma_bf16(acc[mi][ni], ah[mi], bl[ni]);
                    mma_bf16(acc[mi][ni], al[mi], bh[ni]);
                }
        }
        __syncthreads();
    }

    #pragma unroll
    for (int mi = 0; mi < 4; mi++) {
        #pragma unroll
        for (int ni = 0; ni < 4; ni++) {
            int row = bm + wm + mi * 16 + g;
            int col = bn + wn + ni * 8 + 2 * t;
            *(float2*)(C + (size_t)row * N + col) =
                make_float2(acc[mi][ni][0], acc[mi][ni][1]);
            *(float2*)(C + (size_t)(row + 8) * N + col) =
                make_float2(acc[mi][ni][2], acc[mi][ni][3]);
        }
    }
}

// ---------------- tensor-core flash attention (dense / local) ----------------
// mode 0 = dense SDP, 1 = local windowed
#define KTS 72
__global__ __launch_bounds__(128) void flash_mma(const bf16* __restrict__ Qh_,
                                                 const bf16* __restrict__ Ql_,
                                                 const bf16* __restrict__ Kh_,
                                                 const bf16* __restrict__ Kl_,
                                                 const bf16* __restrict__ VTh_,
                                                 const bf16* __restrict__ VTl_,
                                                 float* __restrict__ bout,
                                                 int mode) {
    __shared__ bf16 sKh[64 * KTS], sKl[64 * KTS];
    __shared__ bf16 sVh[64 * KTS], sVl[64 * KTS];

    const int b = blockIdx.z, h = blockIdx.y;
    const int qbase = blockIdx.x * 64;
    const int tid = threadIdx.x;
    const int w = tid >> 5, lane = tid & 31;
    const int g = lane >> 2, t = lane & 3;

    const int tq0 = qbase + w * 16 + g;     // q row for c0/c1
    const int tq1 = tq0 + 8;                // q row for c2/c3

    // Q fragments (resident)
    uint32_t qh[4][4], ql[4][4];
    {
        const size_t b0 = (size_t)(b * LQ + tq0) * DM + h * HD;
        const size_t b1 = (size_t)(b * LQ + tq1) * DM + h * HD;
        #pragma unroll
        for (int kk = 0; kk < 4; kk++) {
            int d0 = kk * 16 + 2 * t;
            qh[kk][0] = *(const uint32_t*)(Qh_ + b0 + d0);
            qh[kk][1] = *(const uint32_t*)(Qh_ + b1 + d0);
            qh[kk][2] = *(const uint32_t*)(Qh_ + b0 + d0 + 8);
            qh[kk][3] = *(const uint32_t*)(Qh_ + b1 + d0 + 8);
            ql[kk][0] = *(const uint32_t*)(Ql_ + b0 + d0);
            ql[kk][1] = *(const uint32_t*)(Ql_ + b1 + d0);
            ql[kk][2] = *(const uint32_t*)(Ql_ + b0 + d0 + 8);
            ql[kk][3] = *(const uint32_t*)(Ql_ + b1 + d0 + 8);
        }
    }

    // local-window bounds per row
    int lo0 = 0, hi0 = LK - 1, lo1 = 0, hi1 = LK - 1;
    if (mode == 1) {
        int c0 = min(4 * tq0, LK - 1), c1 = min(4 * tq1, LK - 1);
        lo0 = max(c0 - 256, 0); hi0 = min(c0 + 256, LK - 1);
        lo1 = max(c1 - 256, 0); hi1 = min(c1 + 256, LK - 1);
    }

    float m0 = -1e30f, m1 = -1e30f, l0 = 0.f, l1 = 0.f;
    float of[8][4];
    #pragma unroll
    for (int n = 0; n < 8; n++)
        #pragma unroll
        for (int r = 0; r < 4; r++) of[n][r] = 0.f;

    int st_lo = 0, st_hi = LK / 64 - 1;
    if (mode == 1) {
        int lo = max(0, 4 * qbase - 256);
        int hi = min(LK - 1, 4 * (qbase + 63) + 256);
        st_lo = lo / 64; st_hi = hi / 64;
    }

    for (int st = st_lo; st <= st_hi; st++) {
        const int s0 = st * 64;
        // cooperative tile loads
        #pragma unroll
        for (int i = 0; i < 4; i++) {
            int idx = i * 128 + tid;
            int r = idx >> 3, c = (idx & 7) * 8;
            size_t gk = (size_t)(b * LK + s0 + r) * DM + h * HD + c;
            *(uint4*)(sKh + r * KTS + c) = *(const uint4*)(Kh_ + gk);
            *(uint4*)(sKl + r * KTS + c) = *(const uint4*)(Kl_ + gk);
            size_t gv = ((size_t)((b * NH + h) * HD + r)) * LK + s0 + c;
            *(uint4*)(sVh + r * KTS + c) = *(const uint4*)(VTh_ + gv);
            *(uint4*)(sVl + r * KTS + c) = *(const uint4*)(VTl_ + gv);
        }
        __syncthreads();

        // scores
        float S[8][4];
        #pragma unroll
        for (int j = 0; j < 8; j++)
            #pragma unroll
            for (int r = 0; r < 4; r++) S[j][r] = 0.f;
        #pragma unroll
        for (int j = 0; j < 8; j++) {
            #pragma unroll
            for (int kk = 0; kk < 4; kk++) {
                const bf16* pk = sKh + (8 * j + g) * KTS + 16 * kk + 2 * t;
                const bf16* pl = sKl + (8 * j + g) * KTS + 16 * kk + 2 * t;
                uint32_t bh[2] = {*(const uint32_t*)pk, *(const uint32_t*)(pk + 8)};
                uint32_t bl[2] = {*(const uint32_t*)pl, *(const uint32_t*)(pl + 8)};
                mma_bf16(S[j], qh[kk], bh);
                mma_bf16(S[j], qh[kk], bl);
                mma_bf16(S[j], ql[kk], bh);
            }
        }
        #pragma unroll
        for (int j = 0; j < 8; j++)
            #pragma unroll
            for (int r = 0; r < 4; r++) S[j][r] *= SCALE;

        if (mode == 1) {
            #pragma unroll
            for (int j = 0; j < 8; j++) {
                int k0i = s0 + 8 * j + 2 * t, k1i = k0i + 1;
                if (k0i < lo0 || k0i > hi0) S[j][0] = -1e30f;
                if (k1i < lo0 || k1i > hi0) S[j][1] = -1e30f;
                if (k0i < lo1 || k0i > hi1) S[j][2] = -1e30f;
                if (k1i < lo1 || k1i > hi1) S[j][3] = -1e30f;
            }
        }

        // online softmax
        float rmax0 = -1e30f, rmax1 = -1e30f;
        #pragma unroll
        for (int j = 0; j < 8; j++) {
            rmax0 = fmaxf(rmax0, fmaxf(S[j][0], S[j][1]));
            rmax1 = fmaxf(rmax1, fmaxf(S[j][2], S[j][3]));
        }
        rmax0 = fmaxf(rmax0, __shfl_xor_sync(0xffffffffu, rmax0, 1));
        rmax0 = fmaxf(rmax0, __shfl_xor_sync(0xffffffffu, rmax0, 2));
        rmax1 = fmaxf(rmax1, __shfl_xor_sync(0xffffffffu, rmax1, 1));
        rmax1 = fmaxf(rmax1, __shfl_xor_sync(0xffffffffu, rmax1, 2));
        float nm0 = fmaxf(m0, rmax0), nm1 = fmaxf(m1, rmax1);
        float corr0 = __expf(m0 - nm0), corr1 = __expf(m1 - nm1);
        float rs0 = 0.f, rs1 = 0.f;
        #pragma unroll
        for (int j = 0; j < 8; j++) {
            float p0 = (S[j][0] < -5e29f) ? 0.f : __expf(S[j][0] - nm0);
            float p1 = (S[j][1] < -5e29f) ? 0.f : __expf(S[j][1] - nm0);
            float p2 = (S[j][2] < -5e29f) ? 0.f : __expf(S[j][2] - nm1);
            float p3 = (S[j][3] < -5e29f) ? 0.f : __expf(S[j][3] - nm1);
            S[j][0] = p0; S[j][1] = p1; S[j][2] = p2; S[j][3] = p3;
            rs0 += p0 + p1; rs1 += p2 + p3;
        }
        rs0 += __shfl_xor_sync(0xffffffffu, rs0, 1);
        rs0 += __shfl_xor_sync(0xffffffffu, rs0, 2);
        rs1 += __shfl_xor_sync(0xffffffffu, rs1, 1);
        rs1 += __shfl_xor_sync(0xffffffffu, rs1, 2);
        l0 = l0 * corr0 + rs0; l1 = l1 * corr1 + rs1;
        m0 = nm0; m1 = nm1;
        #pragma unroll
        for (int n = 0; n < 8; n++) {
            of[n][0] *= corr0; of[n][1] *= corr0;
            of[n][2] *= corr1; of[n][3] *= corr1;
        }

        // PV: P fragments straight from score fragments
        #pragma unroll
        for (int kk = 0; kk < 4; kk++) {
            uint32_t ph[4], pl[4];
            split2(S[2 * kk][0], S[2 * kk][1], ph[0], pl[0]);
            split2(S[2 * kk][2], S[2 * kk][3], ph[1], pl[1]);
            split2(S[2 * kk + 1][0], S[2 * kk + 1][1], ph[2], pl[2]);
            split2(S[2 * kk + 1][2], S[2 * kk + 1][3], ph[3], pl[3]);
            #pragma unroll
            for (int n = 0; n < 8; n++) {
                const bf16* pvh = sVh + (8 * n + g) * KTS + 16 * kk + 2 * t;
                const bf16* pvl = sVl + (8 * n + g) * KTS + 16 * kk + 2 * t;
                uint32_t vh[2] = {*(const uint32_t*)pvh, *(const uint32_t*)(pvh + 8)};
                uint32_t vl[2] = {*(const uint32_t*)pvl, *(const uint32_t*)(pvl + 8)};
                mma_bf16(of[n], ph, vh);
                mma_bf16(of[n], ph, vl);
                mma_bf16(of[n], pl, vh);
            }
        }
        __syncthreads();
    }

    const float inv0 = 1.f / l0, inv1 = 1.f / l1;
    #pragma unroll
    for (int n = 0; n < 8; n++) {
        int dim = h * HD + 8 * n + 2 * t;
        *(float2*)(bout + (size_t)(b * LQ + tq0) * DM + dim) =
            make_float2(of[n][0] * inv0, of[n][1] * inv0);
        *(float2*)(bout + (size_t)(b * LQ + tq1) * DM + dim) =
            make_float2(of[n][2] * inv1, of[n][3] * inv1);
    }
}

// ---------------- fp32 flash (probsparse gather only) -------------------------
#define FQ 64
#define FS 64
#define FP 68
__global__ __launch_bounds__(256) void flash_kernel(const float* __restrict__ Qp,
                                                    const float* __restrict__ Kp,
                                                    const float* __restrict__ Vp,
                                                    float* __restrict__ bout,
                                                    const int* __restrict__ row_map) {
    extern __shared__ float fsm[];
    float* Qs  = fsm;
    float* KVs = fsm + FQ * FP;
    float* Ps  = fsm + 2 * FQ * FP;

    const int b = blockIdx.z, h = blockIdx.y;
    const int tid = threadIdx.x;
    const int ty = tid / 16, tx = tid % 16;

    #pragma unroll
    for (int r = 0; r < 4; r++) {
        int idx = r * 256 + tid;
        int q = idx / 16, dg = (idx % 16) * 4;
        int t; bool valid = true;
        if (q < NTOP) t = row_map[(b * NH + h) * NTOP + q];
        else { t = 0; valid = false; }
        float4 v = valid ? *(const float4*)(Qp + ((size_t)(b * LQ + t)) * DM + h * HD + dg)
                         : make_float4(0.f, 0.f, 0.f, 0.f);
        *(float4*)&Qs[q * FP + dg] = v;
    }
    __syncthreads();

    float m_i[4], l_i[4], acc[4][4];
    #pragma unroll
    for (int i = 0; i < 4; i++) {
        m_i[i] = -1e30f; l_i[i] = 0.f;
        #pragma unroll
        for (int j = 0; j < 4; j++) acc[i][j] = 0.f;
    }

    for (int st = 0; st < LK / FS; st++) {
        const int s0 = st * FS;
        #pragma unroll
        for (int r = 0; r < 4; r++) {
            int idx = r * 256 + tid;
            int s = idx / 16, dg = (idx % 16) * 4;
            *(float4*)&KVs[s * FP + dg] =
                *(const float4*)(Kp + ((size_t)(b * LK + s0 + s)) * DM + h * HD + dg);
        }
        __syncthreads();

        float sc[4][4];
        #pragma unroll
        for (int i = 0; i < 4; i++)
            #pragma unroll
            for (int j = 0; j < 4; j++) sc[i][j] = 0.f;
        #pragma unroll
        for (int d4 = 0; d4 < 16; d4++) {
            float4 qv[4], kv[4];
            #pragma unroll
            for (int i = 0; i < 4; i++) qv[i] = *(float4*)&Qs[(ty * 4 + i) * FP + d4 * 4];
            #pragma unroll
            for (int j = 0; j < 4; j++) kv[j] = *(float4*)&KVs[(tx + 16 * j) * FP + d4 * 4];
            #pragma unroll
            for (int i = 0; i < 4; i++)
                #pragma unroll
                for (int j = 0; j < 4; j++)
                    sc[i][j] += qv[i].x * kv[j].x + qv[i].y * kv[j].y +
                                qv[i].z * kv[j].z + qv[i].w * kv[j].w;
        }
        #pragma unroll
        for (int i = 0; i < 4; i++)
            #pragma unroll
            for (int j = 0; j < 4; j++) sc[i][j] *= SCALE;

        #pragma unroll
        for (int i = 0; i < 4; i++) {
            float rmax = fmaxf(fmaxf(sc[i][0], sc[i][1]), fmaxf(sc[i][2], sc[i][3]));
            #pragma unroll
            for (int off = 1; off < 16; off <<= 1)
                rmax = fmaxf(rmax, __shfl_xor_sync(0xffffffffu, rmax, off, 16));
            float nm = fmaxf(m_i[i], rmax);
            float corr = __expf(m_i[i] - nm);
            float rsum = 0.f;
            float p[4];
            #pragma unroll
            for (int j = 0; j < 4; j++) {
                p[j] = __expf(sc[i][j] - nm);
                rsum += p[j];
            }
            #pragma unroll
            for (int off = 1; off < 16; off <<= 1)
                rsum += __shfl_xor_sync(0xffffffffu, rsum, off, 16);
            l_i[i] = l_i[i] * corr + rsum;
            #pragma unroll
            for (int j = 0; j < 4; j++) acc[i][j] *= corr;
            m_i[i] = nm;
            #pragma unroll
            for (int j = 0; j < 4; j++)
                Ps[(ty * 4 + i) * FP + tx + 16 * j] = p[j];
        }
        __syncthreads();

        #pragma unroll
        for (int r = 0; r < 4; r++) {
            int idx = r * 256 + tid;
            int s = idx / 16, dg = (idx % 16) * 4;
            *(float4*)&KVs[s * FP + dg] =
                *(const float4*)(Vp + ((size_t)(b * LK + s0 + s)) * DM + h * HD + dg);
        }
        __syncthreads();

        #pragma unroll 8
        for (int s = 0; s < FS; s++) {
            float4 vv = *(float4*)&KVs[s * FP + tx * 4];
            #pragma unroll
            for (int i = 0; i < 4; i++) {
                float pi = Ps[(ty * 4 + i) * FP + s];
                acc[i][0] += pi * vv.x; acc[i][1] += pi * vv.y;
                acc[i][2] += pi * vv.z; acc[i][3] += pi * vv.w;
            }
        }
        __syncthreads();
    }

    #pragma unroll
    for (int i = 0; i < 4; i++) {
        int q = ty * 4 + i;
        if (q >= NTOP) continue;
        int t = row_map[(b * NH + h) * NTOP + q];
        float inv = 1.f / l_i[i];
        float4 o = make_float4(acc[i][0] * inv, acc[i][1] * inv,
                               acc[i][2] * inv, acc[i][3] * inv);
        *(float4*)(bout + ((size_t)(b * LQ + t)) * DM + h * HD + tx * 4) = o;
    }
}

// ---------------- linear/cosine KV aggregation -------------------------------
__global__ void kvchunk_kernel(const float* __restrict__ Kp, const float* __restrict__ Vp,
                               float* __restrict__ kvpart, float* __restrict__ kspart,
                               int mode) {
    const int c = blockIdx.x, h = blockIdx.y, b = blockIdx.z;
    __shared__ float sk[32][HD];
    __shared__ float sv[32][HD];
    __shared__ float snorm[32];
    const int tid = threadIdx.x;
    const int dmy = tid / 4, vg = tid % 4;
    float acc[16];
    #pragma unroll
    for (int j = 0; j < 16; j++) acc[j] = 0.f;
    float ksacc = 0.f;
    const int sbeg = c * (LK / 8), send = sbeg + LK / 8;

    for (int s0 = sbeg; s0 < send; s0 += 32) {
        for (int i = tid; i < 32 * HD; i += 256) {
            int ss = i / HD, dd = i % HD;
            size_t base = ((size_t)(b * LK + s0 + ss)) * DM + h * HD + dd;
            sk[ss][dd] = Kp[base];
            sv[ss][dd] = Vp[base];
        }
        __syncthreads();
        if (mode == 1 && tid < 32) {
            float n = 0.f;
            #pragma unroll
            for (int j = 0; j < HD; j++) n += sk[tid][j] * sk[tid][j];
            snorm[tid] = fmaxf(sqrtf(n), 1e-12f);
        }
        __syncthreads();
        #pragma unroll 4
        for (int ss = 0; ss < 32; ss++) {
            float kval = sk[ss][dmy];
            float kf;
            if (mode == 0) kf = (kval > 0.f) ? (kval + 1.f) : __expf(kval);
            else {
                float kn = kval / snorm[ss];
                kf = ((kn > 0.f) ? kn : 0.f) + 1e-6f;
            }
            if (vg == 0) ksacc += kf;
            #pragma unroll
            for (int j = 0; j < 16; j++) acc[j] += kf * sv[ss][vg * 16 + j];
        }
        __syncthreads();
    }
    const int bh = b * NH + h;
    const int NKV = BB * NH * HD * HD;
    #pragma unroll
    for (int j = 0; j < 16; j++)
        kvpart[(size_t)c * NKV + ((size_t)bh * HD + dmy) * HD + vg * 16 + j] = acc[j];
    if (vg == 0) kspart[c * (BB * NH * HD) + bh * HD + dmy] = ksacc;
}

__global__ void kvreduce_kernel(const float* __restrict__ part, float* __restrict__ outp, int n) {
    int idx = blockIdx.x * 256 + threadIdx.x;
    if (idx >= n) return;
    float s = 0.f;
    #pragma unroll
    for (int cc = 0; cc < 8; cc++) s += part[(size_t)cc * n + idx];
    outp[idx] = s;
}

__global__ void lin_out_kernel(const float* __restrict__ Qp, const float* __restrict__ kv,
                               const float* __restrict__ ksum, float* __restrict__ bout,
                               int mode) {
    const int b = blockIdx.z, h = blockIdx.y, t = blockIdx.x;
    __shared__ float sqf[HD];
    __shared__ float red[HD];
    const int tid = threadIdx.x;
    float qv = Qp[((size_t)(b * LQ + t)) * DM + h * HD + tid];
    if (mode == 0) {
        float x = qv * SCALE;
        sqf[tid] = (x > 0.f) ? (x + 1.f) : __expf(x);
    } else {
        red[tid] = qv * qv;
        __syncthreads();
        #pragma unroll
        for (int o = 32; o > 0; o >>= 1) {
            if (tid < o) red[tid] += red[tid + o];
            __syncthreads();
        }
        float nrm = fmaxf(sqrtf(red[0]), 1e-12f);
        float qn = qv / nrm;
        sqf[tid] = ((qn > 0.f) ? qn : 0.f) + 1e-6f;
    }
    __syncthreads();
    const int bh = b * NH + h;
    const float* kvb = kv + (size_t)bh * HD * HD;
    const float* ksb = ksum + (size_t)bh * HD;
    float accv = 0.f, den = 0.f;
    #pragma unroll 8
    for (int d = 0; d < HD; d++) {
        float qf = sqf[d];
        accv += qf * kvb[d * HD + tid];
        den += qf * ksb[d];
    }
    den = fmaxf(den, 1e-6f);
    bout[((size_t)(b * LQ + t)) * DM + h * HD + tid] = accv / den;
}

// ---------------- probsparse helpers -----------------------------------------
__global__ void psparse_m_kernel(const float* __restrict__ Qp, const float* __restrict__ Kp,
                                 const int* __restrict__ sidx, int nsample,
                                 float* __restrict__ Mout) {
    const int b = blockIdx.z, h = blockIdx.y;
    __shared__ float sks[64 * HD];
    const int tid = threadIdx.x;
    for (int i = tid; i < nsample * HD; i += 128) {
        int j = i / HD, dd = i % HD;
        sks[i] = Kp[((size_t)(b * LK + sidx[j])) * DM + h * HD + dd];
    }
    __syncthreads();
    const int t = blockIdx.x * 128 + tid;
    float qr[HD];
    const float* qrow = Qp + ((size_t)(b * LQ + t)) * DM + h * HD;
    #pragma unroll
    for (int j = 0; j < HD; j++) qr[j] = qrow[j];
    float mx = -1e30f, sm = 0.f;
    for (int j = 0; j < nsample; j++) {
        float d = 0.f;
        #pragma unroll
        for (int dd = 0; dd < HD; dd++) d += qr[dd] * sks[j * HD + dd];
        mx = fmaxf(mx, d);
        sm += d;
    }
    Mout[((size_t)(b * NH + h)) * LQ + t] = SCALE * (mx - sm / (float)nsample);
}

__global__ void topk_kernel(const float* __restrict__ M, int* __restrict__ topidx) {
    const int bh = blockIdx.x;
    __shared__ float vals[LQ];
    __shared__ float rv[256];
    __shared__ int ri[256];
    const int tid = threadIdx.x;
    vals[tid] = M[(size_t)bh * LQ + tid];
    vals[tid + 256] = M[(size_t)bh * LQ + tid + 256];
    __syncthreads();
    for (int it = 0; it < NTOP; it++) {
        float v1 = vals[tid], v2 = vals[tid + 256];
        float bv; int bi;
        if (v1 >= v2) { bv = v1; bi = tid; } else { bv = v2; bi = tid + 256; }
        rv[tid] = bv; ri[tid] = bi;
        __syncthreads();
        #pragma unroll
        for (int o = 128; o > 0; o >>= 1) {
            if (tid < o) {
                if (rv[tid + o] > rv[tid] ||
                    (rv[tid + o] == rv[tid] && ri[tid + o] < ri[tid])) {
                    rv[tid] = rv[tid + o]; ri[tid] = ri[tid + o];
                }
            }
            __syncthreads();
        }
        if (tid == 0) {
            topidx[bh * NTOP + it] = ri[0];
            vals[ri[0]] = -1e30f;
        }
        __syncthreads();
    }
}

__global__ void vmean_kernel(const float* __restrict__ Vp, float* __restrict__ vmean) {
    const int bh = blockIdx.x;
    const int b = bh / NH, h = bh % NH;
    const int tid = threadIdx.x;
    const int d = tid % 64, c = tid / 64;
    __shared__ float red[4][64];
    float s = 0.f;
    for (int ss = c * (LK / 4); ss < (c + 1) * (LK / 4); ss++)
        s += Vp[((size_t)(b * LK + ss)) * DM + h * HD + d];
    red[c][d] = s;
    __syncthreads();
    if (tid < 64) {
        float r = red[0][tid] + red[1][tid] + red[2][tid] + red[3][tid];
        vmean[bh * HD + tid] = r * (1.0f / LK);
    }
}

__global__ void fill_vmean_kernel(const float* __restrict__ vmean, float* __restrict__ bout) {
    const int idx = blockIdx.x * 256 + threadIdx.x;
    if (idx >= BB * LQ * DM) return;
    const int d = idx % DM;
    const int bt = idx / DM;
    const int b = bt / LQ;
    const int h = d / HD, dh = d % HD;
    bout[idx] = vmean[(b * NH + h) * HD + dh];
}

// ---------------- fused epilogue ----------------------------------------------
__global__ __launch_bounds__(256) void epilogue_kernel(const float* __restrict__ dec,
                                                       const float* __restrict__ proj,
                                                       const float* __restrict__ rms_w,
                                                       const float* __restrict__ alphas,
                                                       float* __restrict__ out) {
    const int row = blockIdx.x;
    const int tid = threadIdx.x;
    __shared__ float red[256];

    float a[6], w[6];
    #pragma unroll
    for (int i = 0; i < 6; i++) a[i] = alphas[i];
    float mx = a[0];
    #pragma unroll
    for (int i = 1; i < 6; i++) mx = fmaxf(mx, a[i]);
    float ssum = 0.f;
    #pragma unroll
    for (int i = 0; i < 6; i++) { w[i] = __expf(a[i] - mx); ssum += w[i]; }
    #pragma unroll
    for (int i = 0; i < 6; i++) w[i] /= ssum;

    const size_t base = (size_t)row * DM + tid * 4;
    float4 dv = *(const float4*)(dec + base);
    float4 wv = *(const float4*)(rms_w + (size_t)tid * 4);
    float4 oacc = make_float4(w[0] * dv.x, w[0] * dv.y, w[0] * dv.z, w[0] * dv.w);

    #pragma unroll
    for (int br = 0; br < NBR; br++) {
        float4 pv = *(const float4*)(proj + (size_t)br * MROWS * DM + base);
        float4 x = make_float4(dv.x + pv.x, dv.y + pv.y, dv.z + pv.z, dv.w + pv.w);
        float ss = x.x * x.x + x.y * x.y + x.z * x.z + x.w * x.w;
        red[tid] = ss;
        __syncthreads();
        #pragma unroll
        for (int o = 128; o > 0; o >>= 1) {
            if (tid < o) red[tid] += red[tid + o];
            __syncthreads();
        }
        float rs = rsqrtf(red[0] * (1.f / DM) + 1e-6f);
        __syncthreads();
        float wb = w[br + 1];
        oacc.x += wb * x.x * rs * wv.x;
        oacc.y += wb * x.y * rs * wv.y;
        oacc.z += wb * x.z * rs * wv.z;
        oacc.w += wb * x.w * rs * wv.w;
    }
    *(float4*)(out + base) = oacc;
}

// ---------------- launch -------------------------------------------------------
extern "C" void kernel_launch(void* const* d_in, const int* in_sizes, int n_in,
                              void* d_out, int out_size) {
    const float* dec    = (const float*)d_in[0];
    const float* enc    = (const float*)d_in[1];
    const float* Wq     = (const float*)d_in[2];
    const float* Wk     = (const float*)d_in[3];
    const float* Wv     = (const float*)d_in[4];
    const float* Wo     = (const float*)d_in[5];
    const float* rmsw   = (const float*)d_in[6];
    const float* alphas = (const float*)d_in[7];
    const int*   sidx   = (const int*)d_in[8];
    const int nsample   = in_sizes[8];
    float* out = (float*)d_out;

    float *Qs, *Ks, *Vs, *bo, *pj, *kvp, *ksp, *kv, *ks, *Mv, *vm;
    int* tp;
    bf16 *decH, *decL, *encH, *encL, *boH, *boL;
    bf16 *WqH, *WqL, *WkH, *WkL, *WvH, *WvL, *WoH, *WoL;
    bf16 *QH, *QL, *KH, *KL, *VTH, *VTL;
    cudaGetSymbolAddress((void**)&Qs, g_Q);
    cudaGetSymbolAddress((void**)&Ks, g_K);
    cudaGetSymbolAddress((void**)&Vs, g_V);
    cudaGetSymbolAddress((void**)&bo, g_bout);
    cudaGetSymbolAddress((void**)&pj, g_proj);
    cudaGetSymbolAddress((void**)&kvp, g_kvpart);
    cudaGetSymbolAddress((void**)&ksp, g_kspart);
    cudaGetSymbolAddress((void**)&kv, g_kv);
    cudaGetSymbolAddress((void**)&ks, g_ksum);
    cudaGetSymbolAddress((void**)&Mv, g_M);
    cudaGetSymbolAddress((void**)&tp, g_top);
    cudaGetSymbolAddress((void**)&vm, g_vmean);
    cudaGetSymbolAddress((void**)&decH, g_decH);
    cudaGetSymbolAddress((void**)&decL, g_decL);
    cudaGetSymbolAddress((void**)&encH, g_encH);
    cudaGetSymbolAddress((void**)&encL, g_encL);
    cudaGetSymbolAddress((void**)&boH, g_boH);
    cudaGetSymbolAddress((void**)&boL, g_boL);
    cudaGetSymbolAddress((void**)&WqH, g_WqH);
    cudaGetSymbolAddress((void**)&WqL, g_WqL);
    cudaGetSymbolAddress((void**)&WkH, g_WkH);
    cudaGetSymbolAddress((void**)&WkL, g_WkL);
    cudaGetSymbolAddress((void**)&WvH, g_WvH);
    cudaGetSymbolAddress((void**)&WvL, g_WvL);
    cudaGetSymbolAddress((void**)&WoH, g_WoH);
    cudaGetSymbolAddress((void**)&WoL, g_WoL);
    cudaGetSymbolAddress((void**)&QH, g_QH);
    cudaGetSymbolAddress((void**)&QL, g_QL);
    cudaGetSymbolAddress((void**)&KH, g_KH);
    cudaGetSymbolAddress((void**)&KL, g_KL);
    cudaGetSymbolAddress((void**)&VTH, g_VTH);
    cudaGetSymbolAddress((void**)&VTL, g_VTL);

    const int FSMEM = 3 * FQ * FP * sizeof(float);
    cudaFuncSetAttribute(flash_kernel, cudaFuncAttributeMaxDynamicSharedMemorySize, FSMEM);

    const size_t BSTR = (size_t)MROWS * DM;
    const int NKV = BB * NH * HD * HD;
    const int NKS = BB * NH * HD;

    dim3 tgrid(DM / 32, DM / 32);
    dim3 tblk(32, 8);

    // weight + input splits
    splitT_kernel<<<tgrid, tblk>>>(Wq, WqH, WqL);
    splitT_kernel<<<tgrid, tblk>>>(Wk, WkH, WkL);
    splitT_kernel<<<tgrid, tblk>>>(Wv, WvH, WvL);
    splitT_kernel<<<tgrid, tblk>>>(Wo, WoH, WoL);
    split_kernel<<<(MROWS * DM / 4 + 255) / 256, 256>>>(dec, decH, decL, MROWS * DM);
    split_kernel<<<(BB * LK * DM / 4 + 255) / 256, 256>>>(enc, encH, encL, BB * LK * DM);

    // projections
    bgemm<<<dim3(DM / 128, MROWS / 128), 256>>>(decH, decL, WqH, WqL, Qs, MROWS, DM, DM);
    bgemm<<<dim3(DM / 128, BB * LK / 128), 256>>>(encH, encL, WkH, WkL, Ks, BB * LK, DM, DM);
    bgemm<<<dim3(DM / 128, BB * LK / 128), 256>>>(encH, encL, WvH, WvL, Vs, BB * LK, DM, DM);

    // flash-input splits
    split_kernel<<<(MROWS * DM / 4 + 255) / 256, 256>>>(Qs, QH, QL, MROWS * DM);
    split_kernel<<<(BB * LK * DM / 4 + 255) / 256, 256>>>(Ks, KH, KL, BB * LK * DM);
    vtsplit_kernel<<<dim3(LK / 32, NH * 2, BB), tblk>>>(Vs, VTH, VTL);

    // branch 0: dense SDP (tensor-core flash)
    flash_mma<<<dim3(LQ / 64, NH, BB), 128>>>(QH, QL, KH, KL, VTH, VTL, bo, 0);

    // branch 1: linear
    kvchunk_kernel<<<dim3(8, NH, BB), 256>>>(Ks, Vs, kvp, ksp, 0);
    kvreduce_kernel<<<(NKV + 255) / 256, 256>>>(kvp, kv, NKV);
    kvreduce_kernel<<<(NKS + 255) / 256, 256>>>(ksp, ks, NKS);
    lin_out_kernel<<<dim3(LQ, NH, BB), 64>>>(Qs, kv, ks, bo + 1 * BSTR, 0);

    // branch 2: probsparse
    psparse_m_kernel<<<dim3(LQ / 128, NH, BB), 128>>>(Qs, Ks, sidx, nsample, Mv);
    topk_kernel<<<BB * NH, 256>>>(Mv, tp);
    vmean_kernel<<<BB * NH, 256>>>(Vs, vm);
    fill_vmean_kernel<<<(BB * LQ * DM + 255) / 256, 256>>>(vm, bo + 2 * BSTR);
    flash_kernel<<<dim3(1, NH, BB), 256, FSMEM>>>(Qs, Ks, Vs, bo + 2 * BSTR, tp);

    // branch 3: cosine
    kvchunk_kernel<<<dim3(8, NH, BB), 256>>>(Ks, Vs, kvp, ksp, 1);
    kvreduce_kernel<<<(NKV + 255) / 256, 256>>>(kvp, kv, NKV);
    kvreduce_kernel<<<(NKS + 255) / 256, 256>>>(ksp, ks, NKS);
    lin_out_kernel<<<dim3(LQ, NH, BB), 64>>>(Qs, kv, ks, bo + 3 * BSTR, 1);

    // branch 4: local windowed (tensor-core flash)
    flash_mma<<<dim3(LQ / 64, NH, BB), 128>>>(QH, QL, KH, KL, VTH, VTL, bo + 4 * BSTR, 1);

    // batched output projection
    split_kernel<<<(NBR * MROWS * DM / 4 + 255) / 256, 256>>>(bo, boH, boL, NBR * MROWS * DM);
    bgemm<<<dim3(DM / 128, NBR * MROWS / 128), 256>>>(boH, boL, WoH, WoL, pj, NBR * MROWS, DM, DM);

    // fused epilogue
    epilogue_kernel<<<MROWS, 256>>>(dec, pj, rmsw, alphas, out);
}

// round 7
// speedup vs baseline: 9.2634x; 1.2071x over previous
#include <cuda_runtime.h>
#include <cuda_bf16.h>
#include <math.h>
#include <stdint.h>

#define BB 2
#define LQ 512
#define LK 2048
#define DM 1024
#define NH 16
#define HD 64
#define SCALE 0.125f
#define NTOP 31
#define NBR 5
#define MROWS (BB * LQ)
#define NKV (BB * NH * HD * HD)
#define NKS (BB * NH * HD)

typedef __nv_bfloat16 bf16;

// ---------------- scratch ----------------------------------------------------
__device__ float g_Q[BB * LQ * DM];
__device__ float g_K[BB * LK * DM];
__device__ float g_V[BB * LK * DM];
__device__ float g_bout[NBR * MROWS * DM];
__device__ float g_proj[NBR * MROWS * DM];
__device__ float g_kvpart[8 * 2 * NKV];
__device__ float g_kspart[8 * 2 * NKS];
__device__ float g_kv[2 * NKV];
__device__ float g_ksum[2 * NKS];
__device__ float g_M[BB * NH * LQ];
__device__ int   g_top[BB * NH * NTOP];
__device__ float g_vmean[BB * NH * HD];
__device__ float g_vmpart[16 * BB * NH * HD];

// bf16 split buffers
__device__ bf16 g_decH[MROWS * DM],  g_decL[MROWS * DM];
__device__ bf16 g_encH[BB * LK * DM], g_encL[BB * LK * DM];
__device__ bf16 g_boH[NBR * MROWS * DM], g_boL[NBR * MROWS * DM];
__device__ bf16 g_WqH[DM * DM], g_WqL[DM * DM];
__device__ bf16 g_WkH[DM * DM], g_WkL[DM * DM];
__device__ bf16 g_WvH[DM * DM], g_WvL[DM * DM];
__device__ bf16 g_WoH[DM * DM], g_WoL[DM * DM];
// flash inputs
__device__ bf16 g_QH[MROWS * DM],  g_QL[MROWS * DM];
__device__ bf16 g_KH[BB * LK * DM], g_KL[BB * LK * DM];
__device__ bf16 g_VTH[BB * NH * HD * LK], g_VTL[BB * NH * HD * LK];

// ---------------- split fp32 -> (hi, lo) bf16 --------------------------------
__global__ void split_kernel(const float* __restrict__ x, bf16* __restrict__ hi,
                             bf16* __restrict__ lo, int n) {
    int i = (blockIdx.x * 256 + threadIdx.x) * 4;
    if (i >= n) return;
    float4 v = *(const float4*)(x + i);
    bf16 h0 = __float2bfloat16(v.x), h1 = __float2bfloat16(v.y);
    bf16 h2 = __float2bfloat16(v.z), h3 = __float2bfloat16(v.w);
    bf16 l0 = __float2bfloat16(v.x - __bfloat162float(h0));
    bf16 l1 = __float2bfloat16(v.y - __bfloat162float(h1));
    bf16 l2 = __float2bfloat16(v.z - __bfloat162float(h2));
    bf16 l3 = __float2bfloat16(v.w - __bfloat162float(h3));
    __nv_bfloat162* hp = (__nv_bfloat162*)(hi + i);
    __nv_bfloat162* lp = (__nv_bfloat162*)(lo + i);
    hp[0] = __nv_bfloat162(h0, h1); hp[1] = __nv_bfloat162(h2, h3);
    lp[0] = __nv_bfloat162(l0, l1); lp[1] = __nv_bfloat162(l2, l3);
}

// ---------------- split + transpose weights: out[n][k] = W[k][n] -------------
__global__ void splitT_kernel(const float* __restrict__ W, bf16* __restrict__ hiT,
                              bf16* __restrict__ loT) {
    __shared__ float tile[32][33];
    const int bx = blockIdx.x * 32;
    const int by = blockIdx.y * 32;
    const int tx = threadIdx.x, ty = threadIdx.y;
    #pragma unroll
    for (int j = 0; j < 4; j++)
        tile[ty + j * 8][tx] = W[(size_t)(by + ty + j * 8) * DM + bx + tx];
    __syncthreads();
    #pragma unroll
    for (int j = 0; j < 4; j++) {
        float v = tile[tx][ty + j * 8];
        bf16 h = __float2bfloat16(v);
        bf16 l = __float2bfloat16(v - __bfloat162float(h));
        size_t o = (size_t)(bx + ty + j * 8) * DM + by + tx;
        hiT[o] = h; loT[o] = l;
    }
}

// ---------------- transpose-split V: VT[(b,h,d)][s] --------------------------
__global__ void vtsplit_kernel(const float* __restrict__ V, bf16* __restrict__ VTh,
                               bf16* __restrict__ VTl) {
    __shared__ float tile[32][33];
    const int b = blockIdx.z;
    const int h = blockIdx.y >> 1;
    const int d0 = (blockIdx.y & 1) * 32;
    const int s0 = blockIdx.x * 32;
    const int tx = threadIdx.x, ty = threadIdx.y;   // 32 x 8
    #pragma unroll
    for (int j = 0; j < 4; j++)
        tile[ty + j * 8][tx] = V[(size_t)(b * LK + s0 + ty + j * 8) * DM + h * HD + d0 + tx];
    __syncthreads();
    #pragma unroll
    for (int j = 0; j < 4; j++) {
        float v = tile[tx][ty + j * 8];
        bf16 hh = __float2bfloat16(v);
        bf16 ll = __float2bfloat16(v - __bfloat162float(hh));
        size_t o = ((size_t)((b * NH + h) * HD + d0 + ty + j * 8)) * LK + s0 + tx;
        VTh[o] = hh; VTl[o] = ll;
    }
}

// ---------------- mma helpers -------------------------------------------------
__device__ __forceinline__ void mma_bf16(float c[4], const uint32_t a[4], const uint32_t b[2]) {
    asm volatile(
        "mma.sync.aligned.m16n8k16.row.col.f32.bf16.bf16.f32 "
        "{%0,%1,%2,%3}, {%4,%5,%6,%7}, {%8,%9}, {%0,%1,%2,%3};"
        : "+f"(c[0]), "+f"(c[1]), "+f"(c[2]), "+f"(c[3])
        : "r"(a[0]), "r"(a[1]), "r"(a[2]), "r"(a[3]), "r"(b[0]), "r"(b[1]));
}

__device__ __forceinline__ void ldmx4(uint32_t r[4], uint32_t addr) {
    asm volatile("ldmatrix.sync.aligned.m8n8.x4.shared.b16 {%0,%1,%2,%3}, [%4];"
        : "=r"(r[0]), "=r"(r[1]), "=r"(r[2]), "=r"(r[3]) : "r"(addr));
}

__device__ __forceinline__ void split2(float p0, float p1, uint32_t& hi, uint32_t& lo) {
    bf16 h0 = __float2bfloat16(p0), h1 = __float2bfloat16(p1);
    bf16 l0 = __float2bfloat16(p0 - __bfloat162float(h0));
    bf16 l1 = __float2bfloat16(p1 - __bfloat162float(h1));
    __nv_bfloat162 hv(h0, h1), lv(l0, l1);
    hi = *(uint32_t*)&hv; lo = *(uint32_t*)&lv;
}

// ---------------- bf16-split tensor-core GEMM (pipelined + ldmatrix) ---------
#define SPAD 40
__global__ __launch_bounds__(256, 1) void bgemm(const bf16* __restrict__ Ahi,
                                                const bf16* __restrict__ Alo,
                                                const bf16* __restrict__ BhiT,
                                                const bf16* __restrict__ BloT,
                                                float* __restrict__ C,
                                                int M, int N, int K) {
    __shared__ bf16 sAh[128 * SPAD];
    __shared__ bf16 sAl[128 * SPAD];
    __shared__ bf16 sBh[128 * SPAD];
    __shared__ bf16 sBl[128 * SPAD];

    const int bm = blockIdx.y * 128;
    const int bn = blockIdx.x * 128;
    const int tid = threadIdx.x;
    const int wid = tid >> 5, lane = tid & 31;
    const int wm = (wid >> 2) * 64;
    const int wn = (wid & 3) * 32;
    const int g = lane >> 2, t = lane & 3;
    const int lm = lane >> 3, lr = lane & 7;

    // ldmatrix per-lane element offsets (in bytes)
    const uint32_t offA = (uint32_t)(((((lm & 1) << 3) + lr) * SPAD + ((lm >> 1) << 3)) * 2);
    const uint32_t offB = (uint32_t)(((((lm >> 1) << 3) + lr) * SPAD + ((lm & 1) << 3)) * 2);
    const uint32_t sAh32 = (uint32_t)__cvta_generic_to_shared(sAh);
    const uint32_t sAl32 = (uint32_t)__cvta_generic_to_shared(sAl);
    const uint32_t sBh32 = (uint32_t)__cvta_generic_to_shared(sBh);
    const uint32_t sBl32 = (uint32_t)__cvta_generic_to_shared(sBl);

    float acc[4][4][4];
    #pragma unroll
    for (int mi = 0; mi < 4; mi++)
        #pragma unroll
        for (int ni = 0; ni < 4; ni++)
            #pragma unroll
            for (int r = 0; r < 4; r++) acc[mi][ni][r] = 0.f;

    uint4 vah[2], val[2], vbh[2], vbl[2];
    int rows[2], kcs[2];
    #pragma unroll
    for (int i = 0; i < 2; i++) {
        int idx = i * 256 + tid;
        rows[i] = idx >> 2;
        kcs[i] = (idx & 3) * 8;
    }

    // prologue loads (k0 = 0)
    #pragma unroll
    for (int i = 0; i < 2; i++) {
        const size_t ga = (size_t)(bm + rows[i]) * K + kcs[i];
        const size_t gb = (size_t)(bn + rows[i]) * K + kcs[i];
        vah[i] = *(const uint4*)(Ahi + ga);
        val[i] = *(const uint4*)(Alo + ga);
        vbh[i] = *(const uint4*)(BhiT + gb);
        vbl[i] = *(const uint4*)(BloT + gb);
    }

    for (int k0 = 0; k0 < K; k0 += 32) {
        __syncthreads();    // previous compute done reading smem
        #pragma unroll
        for (int i = 0; i < 2; i++) {
            int so = rows[i] * SPAD + kcs[i];
            *(uint4*)(sAh + so) = vah[i];
            *(uint4*)(sAl + so) = val[i];
            *(uint4*)(sBh + so) = vbh[i];
            *(uint4*)(sBl + so) = vbl[i];
        }
        __syncthreads();

        // issue next tile's global loads BEFORE compute (latency hidden by MMAs)
        if (k0 + 32 < K) {
            #pragma unroll
            for (int i = 0; i < 2; i++) {
                const size_t ga = (size_t)(bm + rows[i]) * K + k0 + 32 + kcs[i];
                const size_t gb = (size_t)(bn + rows[i]) * K + k0 + 32 + kcs[i];
                vah[i] = *(const uint4*)(Ahi + ga);
                val[i] = *(const uint4*)(Alo + ga);
                vbh[i] = *(const uint4*)(BhiT + gb);
                vbl[i] = *(const uint4*)(BloT + gb);
            }
        }

        #pragma unroll
        for (int ks = 0; ks < 32; ks += 16) {
            uint32_t ah[4][4], al[4][4], bh[2][4], bl[2][4];
            #pragma unroll
            for (int mi = 0; mi < 4; mi++) {
                uint32_t d = (uint32_t)(((wm + mi * 16) * SPAD + ks) * 2);
                ldmx4(ah[mi], sAh32 + d + offA);
                ldmx4(al[mi], sAl32 + d + offA);
            }
            #pragma unroll
            for (int np = 0; np < 2; np++) {
                uint32_t d = (uint32_t)(((wn + np * 16) * SPAD + ks) * 2);
                ldmx4(bh[np], sBh32 + d + offB);
                ldmx4(bl[np], sBl32 + d + offB);
            }
            #pragma unroll
            for (int mi = 0; mi < 4; mi++)
                #pragma unroll
                for (int ni = 0; ni < 4; ni++) {
                    const uint32_t* BH = &bh[ni >> 1][(ni & 1) * 2];
                    const uint32_t* BL = &bl[ni >> 1][(ni & 1) * 2];
                    mma_bf16(acc[mi][ni], ah[mi], BH);
                    mma_bf16(acc[mi][ni], ah[mi], BL);
                    mma_bf16(acc[mi][ni], al[mi], BH);
                }
        }
    }

    #pragma unroll
    for (int mi = 0; mi < 4; mi++) {
        #pragma unroll
        for (int ni = 0; ni < 4; ni++) {
            int row = bm + wm + mi * 16 + g;
            int col = bn + wn + ni * 8 + 2 * t;
            *(float2*)(C + (size_t)row * N + col) =
                make_float2(acc[mi][ni][0], acc[mi][ni][1]);
            *(float2*)(C + (size_t)(row + 8) * N + col) =
                make_float2(acc[mi][ni][2], acc[mi][ni][3]);
        }
    }
}

// ---------------- tensor-core flash attention (dense / local) ----------------
#define KTS 72
__global__ __launch_bounds__(128) void flash_mma(const bf16* __restrict__ Qh_,
                                                 const bf16* __restrict__ Ql_,
                                                 const bf16* __restrict__ Kh_,
                                                 const bf16* __restrict__ Kl_,
                                                 const bf16* __restrict__ VTh_,
                                                 const bf16* __restrict__ VTl_,
                                                 float* __restrict__ bout,
                                                 int mode) {
    __shared__ bf16 sKh[64 * KTS], sKl[64 * KTS];
    __shared__ bf16 sVh[64 * KTS], sVl[64 * KTS];

    const int b = blockIdx.z, h = blockIdx.y;
    const int qbase = blockIdx.x * 64;
    const int tid = threadIdx.x;
    const int w = tid >> 5, lane = tid & 31;
    const int g = lane >> 2, t = lane & 3;

    const int tq0 = qbase + w * 16 + g;
    const int tq1 = tq0 + 8;

    uint32_t qh[4][4], ql[4][4];
    {
        const size_t b0 = (size_t)(b * LQ + tq0) * DM + h * HD;
        const size_t b1 = (size_t)(b * LQ + tq1) * DM + h * HD;
        #pragma unroll
        for (int kk = 0; kk < 4; kk++) {
            int d0 = kk * 16 + 2 * t;
            qh[kk][0] = *(const uint32_t*)(Qh_ + b0 + d0);
            qh[kk][1] = *(const uint32_t*)(Qh_ + b1 + d0);
            qh[kk][2] = *(const uint32_t*)(Qh_ + b0 + d0 + 8);
            qh[kk][3] = *(const uint32_t*)(Qh_ + b1 + d0 + 8);
            ql[kk][0] = *(const uint32_t*)(Ql_ + b0 + d0);
            ql[kk][1] = *(const uint32_t*)(Ql_ + b1 + d0);
            ql[kk][2] = *(const uint32_t*)(Ql_ + b0 + d0 + 8);
            ql[kk][3] = *(const uint32_t*)(Ql_ + b1 + d0 + 8);
        }
    }

    int lo0 = 0, hi0 = LK - 1, lo1 = 0, hi1 = LK - 1;
    if (mode == 1) {
        int c0 = min(4 * tq0, LK - 1), c1 = min(4 * tq1, LK - 1);
        lo0 = max(c0 - 256, 0); hi0 = min(c0 + 256, LK - 1);
        lo1 = max(c1 - 256, 0); hi1 = min(c1 + 256, LK - 1);
    }

    float m0 = -1e30f, m1 = -1e30f, l0 = 0.f, l1 = 0.f;
    float of[8][4];
    #pragma unroll
    for (int n = 0; n < 8; n++)
        #pragma unroll
        for (int r = 0; r < 4; r++) of[n][r] = 0.f;

    int st_lo = 0, st_hi = LK / 64 - 1;
    if (mode == 1) {
        int lo = max(0, 4 * qbase - 256);
        int hi = min(LK - 1, 4 * (qbase + 63) + 256);
        st_lo = lo / 64; st_hi = hi / 64;
    }

    for (int st = st_lo; st <= st_hi; st++) {
        const int s0 = st * 64;
        #pragma unroll
        for (int i = 0; i < 4; i++) {
            int idx = i * 128 + tid;
            int r = idx >> 3, c = (idx & 7) * 8;
            size_t gk = (size_t)(b * LK + s0 + r) * DM + h * HD + c;
            *(uint4*)(sKh + r * KTS + c) = *(const uint4*)(Kh_ + gk);
            *(uint4*)(sKl + r * KTS + c) = *(const uint4*)(Kl_ + gk);
            size_t gv = ((size_t)((b * NH + h) * HD + r)) * LK + s0 + c;
            *(uint4*)(sVh + r * KTS + c) = *(const uint4*)(VTh_ + gv);
            *(uint4*)(sVl + r * KTS + c) = *(const uint4*)(VTl_ + gv);
        }
        __syncthreads();

        float S[8][4];
        #pragma unroll
        for (int j = 0; j < 8; j++)
            #pragma unroll
            for (int r = 0; r < 4; r++) S[j][r] = 0.f;
        #pragma unroll
        for (int j = 0; j < 8; j++) {
            #pragma unroll
            for (int kk = 0; kk < 4; kk++) {
                const bf16* pk = sKh + (8 * j + g) * KTS + 16 * kk + 2 * t;
                const bf16* pl = sKl + (8 * j + g) * KTS + 16 * kk + 2 * t;
                uint32_t bh[2] = {*(const uint32_t*)pk, *(const uint32_t*)(pk + 8)};
                uint32_t bl[2] = {*(const uint32_t*)pl, *(const uint32_t*)(pl + 8)};
                mma_bf16(S[j], qh[kk], bh);
                mma_bf16(S[j], qh[kk], bl);
                mma_bf16(S[j], ql[kk], bh);
            }
        }
        #pragma unroll
        for (int j = 0; j < 8; j++)
            #pragma unroll
            for (int r = 0; r < 4; r++) S[j][r] *= SCALE;

        if (mode == 1) {
            #pragma unroll
            for (int j = 0; j < 8; j++) {
                int k0i = s0 + 8 * j + 2 * t, k1i = k0i + 1;
                if (k0i < lo0 || k0i > hi0) S[j][0] = -1e30f;
                if (k1i < lo0 || k1i > hi0) S[j][1] = -1e30f;
                if (k0i < lo1 || k0i > hi1) S[j][2] = -1e30f;
                if (k1i < lo1 || k1i > hi1) S[j][3] = -1e30f;
            }
        }

        float rmax0 = -1e30f, rmax1 = -1e30f;
        #pragma unroll
        for (int j = 0; j < 8; j++) {
            rmax0 = fmaxf(rmax0, fmaxf(S[j][0], S[j][1]));
            rmax1 = fmaxf(rmax1, fmaxf(S[j][2], S[j][3]));
        }
        rmax0 = fmaxf(rmax0, __shfl_xor_sync(0xffffffffu, rmax0, 1));
        rmax0 = fmaxf(rmax0, __shfl_xor_sync(0xffffffffu, rmax0, 2));
        rmax1 = fmaxf(rmax1, __shfl_xor_sync(0xffffffffu, rmax1, 1));
        rmax1 = fmaxf(rmax1, __shfl_xor_sync(0xffffffffu, rmax1, 2));
        float nm0 = fmaxf(m0, rmax0), nm1 = fmaxf(m1, rmax1);
        float corr0 = __expf(m0 - nm0), corr1 = __expf(m1 - nm1);
        float rs0 = 0.f, rs1 = 0.f;
        #pragma unroll
        for (int j = 0; j < 8; j++) {
            float p0 = (S[j][0] < -5e29f) ? 0.f : __expf(S[j][0] - nm0);
            float p1 = (S[j][1] < -5e29f) ? 0.f : __expf(S[j][1] - nm0);
            float p2 = (S[j][2] < -5e29f) ? 0.f : __expf(S[j][2] - nm1);
            float p3 = (S[j][3] < -5e29f) ? 0.f : __expf(S[j][3] - nm1);
            S[j][0] = p0; S[j][1] = p1; S[j][2] = p2; S[j][3] = p3;
            rs0 += p0 + p1; rs1 += p2 + p3;
        }
        rs0 += __shfl_xor_sync(0xffffffffu, rs0, 1);
        rs0 += __shfl_xor_sync(0xffffffffu, rs0, 2);
        rs1 += __shfl_xor_sync(0xffffffffu, rs1, 1);
        rs1 += __shfl_xor_sync(0xffffffffu, rs1, 2);
        l0 = l0 * corr0 + rs0; l1 = l1 * corr1 + rs1;
        m0 = nm0; m1 = nm1;
        #pragma unroll
        for (int n = 0; n < 8; n++) {
            of[n][0] *= corr0; of[n][1] *= corr0;
            of[n][2] *= corr1; of[n][3] *= corr1;
        }

        #pragma unroll
        for (int kk = 0; kk < 4; kk++) {
            uint32_t ph[4], pl[4];
            split2(S[2 * kk][0], S[2 * kk][1], ph[0], pl[0]);
            split2(S[2 * kk][2], S[2 * kk][3], ph[1], pl[1]);
            split2(S[2 * kk + 1][0], S[2 * kk + 1][1], ph[2], pl[2]);
            split2(S[2 * kk + 1][2], S[2 * kk + 1][3], ph[3], pl[3]);
            #pragma unroll
            for (int n = 0; n < 8; n++) {
                const bf16* pvh = sVh + (8 * n + g) * KTS + 16 * kk + 2 * t;
                const bf16* pvl = sVl + (8 * n + g) * KTS + 16 * kk + 2 * t;
                uint32_t vh[2] = {*(const uint32_t*)pvh, *(const uint32_t*)(pvh + 8)};
                uint32_t vl[2] = {*(const uint32_t*)pvl, *(const uint32_t*)(pvl + 8)};
                mma_bf16(of[n], ph, vh);
                mma_bf16(of[n], ph, vl);
                mma_bf16(of[n], pl, vh);
            }
        }
        __syncthreads();
    }

    const float inv0 = 1.f / l0, inv1 = 1.f / l1;
    #pragma unroll
    for (int n = 0; n < 8; n++) {
        int dim = h * HD + 8 * n + 2 * t;
        *(float2*)(bout + (size_t)(b * LQ + tq0) * DM + dim) =
            make_float2(of[n][0] * inv0, of[n][1] * inv0);
        *(float2*)(bout + (size_t)(b * LQ + tq1) * DM + dim) =
            make_float2(of[n][2] * inv1, of[n][3] * inv1);
    }
}

// ---------------- fp32 flash (probsparse gather only) -------------------------
#define FQ 64
#define FS 64
#define FP 68
__global__ __launch_bounds__(256) void flash_kernel(const float* __restrict__ Qp,
                                                    const float* __restrict__ Kp,
                                                    const float* __restrict__ Vp,
                                                    float* __restrict__ bout,
                                                    const int* __restrict__ row_map) {
    extern __shared__ float fsm[];
    float* Qs  = fsm;
    float* KVs = fsm + FQ * FP;
    float* Ps  = fsm + 2 * FQ * FP;

    const int b = blockIdx.z, h = blockIdx.y;
    const int tid = threadIdx.x;
    const int ty = tid / 16, tx = tid % 16;

    #pragma unroll
    for (int r = 0; r < 4; r++) {
        int idx = r * 256 + tid;
        int q = idx / 16, dg = (idx % 16) * 4;
        int t; bool valid = true;
        if (q < NTOP) t = row_map[(b * NH + h) * NTOP + q];
        else { t = 0; valid = false; }
        float4 v = valid ? *(const float4*)(Qp + ((size_t)(b * LQ + t)) * DM + h * HD + dg)
                         : make_float4(0.f, 0.f, 0.f, 0.f);
        *(float4*)&Qs[q * FP + dg] = v;
    }
    __syncthreads();

    float m_i[4], l_i[4], acc[4][4];
    #pragma unroll
    for (int i = 0; i < 4; i++) {
        m_i[i] = -1e30f; l_i[i] = 0.f;
        #pragma unroll
        for (int j = 0; j < 4; j++) acc[i][j] = 0.f;
    }

    for (int st = 0; st < LK / FS; st++) {
        const int s0 = st * FS;
        #pragma unroll
        for (int r = 0; r < 4; r++) {
            int idx = r * 256 + tid;
            int s = idx / 16, dg = (idx % 16) * 4;
            *(float4*)&KVs[s * FP + dg] =
                *(const float4*)(Kp + ((size_t)(b * LK + s0 + s)) * DM + h * HD + dg);
        }
        __syncthreads();

        float sc[4][4];
        #pragma unroll
        for (int i = 0; i < 4; i++)
            #pragma unroll
            for (int j = 0; j < 4; j++) sc[i][j] = 0.f;
        #pragma unroll
        for (int d4 = 0; d4 < 16; d4++) {
            float4 qv[4], kv[4];
            #pragma unroll
            for (int i = 0; i < 4; i++) qv[i] = *(float4*)&Qs[(ty * 4 + i) * FP + d4 * 4];
            #pragma unroll
            for (int j = 0; j < 4; j++) kv[j] = *(float4*)&KVs[(tx + 16 * j) * FP + d4 * 4];
            #pragma unroll
            for (int i = 0; i < 4; i++)
                #pragma unroll
                for (int j = 0; j < 4; j++)
                    sc[i][j] += qv[i].x * kv[j].x + qv[i].y * kv[j].y +
                                qv[i].z * kv[j].z + qv[i].w * kv[j].w;
        }
        #pragma unroll
        for (int i = 0; i < 4; i++)
            #pragma unroll
            for (int j = 0; j < 4; j++) sc[i][j] *= SCALE;

        #pragma unroll
        for (int i = 0; i < 4; i++) {
            float rmax = fmaxf(fmaxf(sc[i][0], sc[i][1]), fmaxf(sc[i][2], sc[i][3]));
            #pragma unroll
            for (int off = 1; off < 16; off <<= 1)
                rmax = fmaxf(rmax, __shfl_xor_sync(0xffffffffu, rmax, off, 16));
            float nm = fmaxf(m_i[i], rmax);
            float corr = __expf(m_i[i] - nm);
            float rsum = 0.f;
            float p[4];
            #pragma unroll
            for (int j = 0; j < 4; j++) {
                p[j] = __expf(sc[i][j] - nm);
                rsum += p[j];
            }
            #pragma unroll
            for (int off = 1; off < 16; off <<= 1)
                rsum += __shfl_xor_sync(0xffffffffu, rsum, off, 16);
            l_i[i] = l_i[i] * corr + rsum;
            #pragma unroll
            for (int j = 0; j < 4; j++) acc[i][j] *= corr;
            m_i[i] = nm;
            #pragma unroll
            for (int j = 0; j < 4; j++)
                Ps[(ty * 4 + i) * FP + tx + 16 * j] = p[j];
        }
        __syncthreads();

        #pragma unroll
        for (int r = 0; r < 4; r++) {
            int idx = r * 256 + tid;
            int s = idx / 16, dg = (idx % 16) * 4;
            *(float4*)&KVs[s * FP + dg] =
                *(const float4*)(Vp + ((size_t)(b * LK + s0 + s)) * DM + h * HD + dg);
        }
        __syncthreads();

        #pragma unroll 8
        for (int s = 0; s < FS; s++) {
            float4 vv = *(float4*)&KVs[s * FP + tx * 4];
            #pragma unroll
            for (int i = 0; i < 4; i++) {
                float pi = Ps[(ty * 4 + i) * FP + s];
                acc[i][0] += pi * vv.x; acc[i][1] += pi * vv.y;
                acc[i][2] += pi * vv.z; acc[i][3] += pi * vv.w;
            }
        }
        __syncthreads();
    }

    #pragma unroll
    for (int i = 0; i < 4; i++) {
        int q = ty * 4 + i;
        if (q >= NTOP) continue;
        int t = row_map[(b * NH + h) * NTOP + q];
        float inv = 1.f / l_i[i];
        float4 o = make_float4(acc[i][0] * inv, acc[i][1] * inv,
                               acc[i][2] * inv, acc[i][3] * inv);
        *(float4*)(bout + ((size_t)(b * LQ + t)) * DM + h * HD + tx * 4) = o;
    }
}

// ---------------- dual-mode KV aggregation (linear + cosine in one pass) -----
__global__ void kvchunk2_kernel(const float* __restrict__ Kp, const float* __restrict__ Vp,
                                float* __restrict__ kvpart, float* __restrict__ kspart) {
    const int c = blockIdx.x, h = blockIdx.y, b = blockIdx.z;
    __shared__ float sk[32][HD];
    __shared__ float sv[32][HD];
    __shared__ float snorm[32];
    const int tid = threadIdx.x;
    const int dmy = tid / 4, vg = tid % 4;
    float acc0[16], acc1[16];
    #pragma unroll
    for (int j = 0; j < 16; j++) { acc0[j] = 0.f; acc1[j] = 0.f; }
    float ks0 = 0.f, ks1 = 0.f;
    const int sbeg = c * (LK / 8), send = sbeg + LK / 8;

    for (int s0 = sbeg; s0 < send; s0 += 32) {
        for (int i = tid; i < 32 * HD; i += 256) {
            int ss = i / HD, dd = i % HD;
            size_t base = ((size_t)(b * LK + s0 + ss)) * DM + h * HD + dd;
            sk[ss][dd] = Kp[base];
            sv[ss][dd] = Vp[base];
        }
        __syncthreads();
        if (tid < 32) {
            float n = 0.f;
            #pragma unroll
            for (int j = 0; j < HD; j++) n += sk[tid][j] * sk[tid][j];
            snorm[tid] = fmaxf(sqrtf(n), 1e-12f);
        }
        __syncthreads();
        #pragma unroll 4
        for (int ss = 0; ss < 32; ss++) {
            float kval = sk[ss][dmy];
            float kf0 = (kval > 0.f) ? (kval + 1.f) : __expf(kval);
            float kn = kval / snorm[ss];
            float kf1 = ((kn > 0.f) ? kn : 0.f) + 1e-6f;
            if (vg == 0) { ks0 += kf0; ks1 += kf1; }
            #pragma unroll
            for (int j = 0; j < 16; j++) {
                float vv = sv[ss][vg * 16 + j];
                acc0[j] += kf0 * vv;
                acc1[j] += kf1 * vv;
            }
        }
        __syncthreads();
    }
    const int bh = b * NH + h;
    #pragma unroll
    for (int j = 0; j < 16; j++) {
        size_t o = ((size_t)bh * HD + dmy) * HD + vg * 16 + j;
        kvpart[(size_t)c * (2 * NKV) + o] = acc0[j];
        kvpart[(size_t)c * (2 * NKV) + NKV + o] = acc1[j];
    }
    if (vg == 0) {
        kspart[c * (2 * NKS) + bh * HD + dmy] = ks0;
        kspart[c * (2 * NKS) + NKS + bh * HD + dmy] = ks1;
    }
}

__global__ void kvreduce_kernel(const float* __restrict__ part, float* __restrict__ outp, int n) {
    int idx = blockIdx.x * 256 + threadIdx.x;
    if (idx >= n) return;
    float s = 0.f;
    #pragma unroll
    for (int cc = 0; cc < 8; cc++) s += part[(size_t)cc * n + idx];
    outp[idx] = s;
}

__global__ void lin_out_kernel(const float* __restrict__ Qp, const float* __restrict__ kv,
                               const float* __restrict__ ksum, float* __restrict__ bout,
                               int mode) {
    const int b = blockIdx.z, h = blockIdx.y, t = blockIdx.x;
    __shared__ float sqf[HD];
    __shared__ float red[HD];
    const int tid = threadIdx.x;
    float qv = Qp[((size_t)(b * LQ + t)) * DM + h * HD + tid];
    if (mode == 0) {
        float x = qv * SCALE;
        sqf[tid] = (x > 0.f) ? (x + 1.f) : __expf(x);
    } else {
        red[tid] = qv * qv;
        __syncthreads();
        #pragma unroll
        for (int o = 32; o > 0; o >>= 1) {
            if (tid < o) red[tid] += red[tid + o];
            __syncthreads();
        }
        float nrm = fmaxf(sqrtf(red[0]), 1e-12f);
        float qn = qv / nrm;
        sqf[tid] = ((qn > 0.f) ? qn : 0.f) + 1e-6f;
    }
    __syncthreads();
    const int bh = b * NH + h;
    const float* kvb = kv + (size_t)bh * HD * HD;
    const float* ksb = ksum + (size_t)bh * HD;
    float accv = 0.f, den = 0.f;
    #pragma unroll 8
    for (int d = 0; d < HD; d++) {
        float qf = sqf[d];
        accv += qf * kvb[d * HD + tid];
        den += qf * ksb[d];
    }
    den = fmaxf(den, 1e-6f);
    bout[((size_t)(b * LQ + t)) * DM + h * HD + tid] = accv / den;
}

// ---------------- probsparse helpers -----------------------------------------
__global__ void psparse_m_kernel(const float* __restrict__ Qp, const float* __restrict__ Kp,
                                 const int* __restrict__ sidx, int nsample,
                                 float* __restrict__ Mout) {
    const int b = blockIdx.z, h = blockIdx.y;
    __shared__ float sks[64 * HD];
    const int tid = threadIdx.x;
    for (int i = tid; i < nsample * HD; i += 128) {
        int j = i / HD, dd = i % HD;
        sks[i] = Kp[((size_t)(b * LK + sidx[j])) * DM + h * HD + dd];
    }
    __syncthreads();
    const int t = blockIdx.x * 128 + tid;
    float qr[HD];
    const float* qrow = Qp + ((size_t)(b * LQ + t)) * DM + h * HD;
    #pragma unroll
    for (int j = 0; j < HD; j++) qr[j] = qrow[j];
    float mx = -1e30f, sm = 0.f;
    for (int j = 0; j < nsample; j++) {
        float d = 0.f;
        #pragma unroll
        for (int dd = 0; dd < HD; dd++) d += qr[dd] * sks[j * HD + dd];
        mx = fmaxf(mx, d);
        sm += d;
    }
    Mout[((size_t)(b * NH + h)) * LQ + t] = SCALE * (mx - sm / (float)nsample);
}

__global__ void topk_kernel(const float* __restrict__ M, int* __restrict__ topidx) {
    const int bh = blockIdx.x;
    __shared__ float vals[LQ];
    __shared__ float rv[256];
    __shared__ int ri[256];
    const int tid = threadIdx.x;
    vals[tid] = M[(size_t)bh * LQ + tid];
    vals[tid + 256] = M[(size_t)bh * LQ + tid + 256];
    __syncthreads();
    for (int it = 0; it < NTOP; it++) {
        float v1 = vals[tid], v2 = vals[tid + 256];
        float bv; int bi;
        if (v1 >= v2) { bv = v1; bi = tid; } else { bv = v2; bi = tid + 256; }
        rv[tid] = bv; ri[tid] = bi;
        __syncthreads();
        #pragma unroll
        for (int o = 128; o > 0; o >>= 1) {
            if (tid < o) {
                if (rv[tid + o] > rv[tid] ||
                    (rv[tid + o] == rv[tid] && ri[tid + o] < ri[tid])) {
                    rv[tid] = rv[tid + o]; ri[tid] = ri[tid + o];
                }
            }
            __syncthreads();
        }
        if (tid == 0) {
            topidx[bh * NTOP + it] = ri[0];
            vals[ri[0]] = -1e30f;
        }
        __syncthreads();
    }
}

__global__ void vmean_part_kernel(const float* __restrict__ Vp, float* __restrict__ part) {
    const int c = blockIdx.x, bh = blockIdx.y;
    const int b = bh / NH, h = bh % NH;
    const int d = threadIdx.x;   // 64
    float s = 0.f;
    const int beg = c * (LK / 16);
    for (int ss = beg; ss < beg + LK / 16; ss++)
        s += Vp[((size_t)(b * LK + ss)) * DM + h * HD + d];
    part[(c * BB * NH + bh) * HD + d] = s;
}

__global__ void vmean_reduce_kernel(const float* __restrict__ part, float* __restrict__ vmean) {
    const int idx = blockIdx.x * 64 + threadIdx.x;   // BB*NH*HD = 2048
    float s = 0.f;
    #pragma unroll
    for (int c = 0; c < 16; c++) s += part[c * (BB * NH * HD) + idx];
    vmean[idx] = s * (1.0f / LK);
}

__global__ void fill_vmean_kernel(const float* __restrict__ vmean, float* __restrict__ bout) {
    const int idx = blockIdx.x * 256 + threadIdx.x;
    if (idx >= BB * LQ * DM) return;
    const int d = idx % DM;
    const int bt = idx / DM;
    const int b = bt / LQ;
    const int h = d / HD, dh = d % HD;
    bout[idx] = vmean[(b * NH + h) * HD + dh];
}

// ---------------- fused epilogue ----------------------------------------------
__global__ __launch_bounds__(256) void epilogue_kernel(const float* __restrict__ dec,
                                                       const float* __restrict__ proj,
                                                       const float* __restrict__ rms_w,
                                                       const float* __restrict__ alphas,
                                                       float* __restrict__ out) {
    const int row = blockIdx.x;
    const int tid = threadIdx.x;
    __shared__ float red[256];

    float a[6], w[6];
    #pragma unroll
    for (int i = 0; i < 6; i++) a[i] = alphas[i];
    float mx = a[0];
    #pragma unroll
    for (int i = 1; i < 6; i++) mx = fmaxf(mx, a[i]);
    float ssum = 0.f;
    #pragma unroll
    for (int i = 0; i < 6; i++) { w[i] = __expf(a[i] - mx); ssum += w[i]; }
    #pragma unroll
    for (int i = 0; i < 6; i++) w[i] /= ssum;

    const size_t base = (size_t)row * DM + tid * 4;
    float4 dv = *(const float4*)(dec + base);
    float4 wv = *(const float4*)(rms_w + (size_t)tid * 4);
    float4 oacc = make_float4(w[0] * dv.x, w[0] * dv.y, w[0] * dv.z, w[0] * dv.w);

    #pragma unroll
    for (int br = 0; br < NBR; br++) {
        float4 pv = *(const float4*)(proj + (size_t)br * MROWS * DM + base);
        float4 x = make_float4(dv.x + pv.x, dv.y + pv.y, dv.z + pv.z, dv.w + pv.w);
        float ss = x.x * x.x + x.y * x.y + x.z * x.z + x.w * x.w;
        red[tid] = ss;
        __syncthreads();
        #pragma unroll
        for (int o = 128; o > 0; o >>= 1) {
            if (tid < o) red[tid] += red[tid + o];
            __syncthreads();
        }
        float rs = rsqrtf(red[0] * (1.f / DM) + 1e-6f);
        __syncthreads();
        float wb = w[br + 1];
        oacc.x += wb * x.x * rs * wv.x;
        oacc.y += wb * x.y * rs * wv.y;
        oacc.z += wb * x.z * rs * wv.z;
        oacc.w += wb * x.w * rs * wv.w;
    }
    *(float4*)(out + base) = oacc;
}

// ---------------- launch -------------------------------------------------------
extern "C" void kernel_launch(void* const* d_in, const int* in_sizes, int n_in,
                              void* d_out, int out_size) {
    const float* dec    = (const float*)d_in[0];
    const float* enc    = (const float*)d_in[1];
    const float* Wq     = (const float*)d_in[2];
    const float* Wk     = (const float*)d_in[3];
    const float* Wv     = (const float*)d_in[4];
    const float* Wo     = (const float*)d_in[5];
    const float* rmsw   = (const float*)d_in[6];
    const float* alphas = (const float*)d_in[7];
    const int*   sidx   = (const int*)d_in[8];
    const int nsample   = in_sizes[8];
    float* out = (float*)d_out;

    float *Qs, *Ks, *Vs, *bo, *pj, *kvp, *ksp, *kv, *ks, *Mv, *vm, *vmp;
    int* tp;
    bf16 *decH, *decL, *encH, *encL, *boH, *boL;
    bf16 *WqH, *WqL, *WkH, *WkL, *WvH, *WvL, *WoH, *WoL;
    bf16 *QH, *QL, *KH, *KL, *VTH, *VTL;
    cudaGetSymbolAddress((void**)&Qs, g_Q);
    cudaGetSymbolAddress((void**)&Ks, g_K);
    cudaGetSymbolAddress((void**)&Vs, g_V);
    cudaGetSymbolAddress((void**)&bo, g_bout);
    cudaGetSymbolAddress((void**)&pj, g_proj);
    cudaGetSymbolAddress((void**)&kvp, g_kvpart);
    cudaGetSymbolAddress((void**)&ksp, g_kspart);
    cudaGetSymbolAddress((void**)&kv, g_kv);
    cudaGetSymbolAddress((void**)&ks, g_ksum);
    cudaGetSymbolAddress((void**)&Mv, g_M);
    cudaGetSymbolAddress((void**)&tp, g_top);
    cudaGetSymbolAddress((void**)&vm, g_vmean);
    cudaGetSymbolAddress((void**)&vmp, g_vmpart);
    cudaGetSymbolAddress((void**)&decH, g_decH);
    cudaGetSymbolAddress((void**)&decL, g_decL);
    cudaGetSymbolAddress((void**)&encH, g_encH);
    cudaGetSymbolAddress((void**)&encL, g_encL);
    cudaGetSymbolAddress((void**)&boH, g_boH);
    cudaGetSymbolAddress((void**)&boL, g_boL);
    cudaGetSymbolAddress((void**)&WqH, g_WqH);
    cudaGetSymbolAddress((void**)&WqL, g_WqL);
    cudaGetSymbolAddress((void**)&WkH, g_WkH);
    cudaGetSymbolAddress((void**)&WkL, g_WkL);
    cudaGetSymbolAddress((void**)&WvH, g_WvH);
    cudaGetSymbolAddress((void**)&WvL, g_WvL);
    cudaGetSymbolAddress((void**)&WoH, g_WoH);
    cudaGetSymbolAddress((void**)&WoL, g_WoL);
    cudaGetSymbolAddress((void**)&QH, g_QH);
    cudaGetSymbolAddress((void**)&QL, g_QL);
    cudaGetSymbolAddress((void**)&KH, g_KH);
    cudaGetSymbolAddress((void**)&KL, g_KL);
    cudaGetSymbolAddress((void**)&VTH, g_VTH);
    cudaGetSymbolAddress((void**)&VTL, g_VTL);

    const int FSMEM = 3 * FQ * FP * sizeof(float);
    cudaFuncSetAttribute(flash_kernel, cudaFuncAttributeMaxDynamicSharedMemorySize, FSMEM);

    const size_t BSTR = (size_t)MROWS * DM;

    dim3 tgrid(DM / 32, DM / 32);
    dim3 tblk(32, 8);

    // weight + input splits
    splitT_kernel<<<tgrid, tblk>>>(Wq, WqH, WqL);
    splitT_kernel<<<tgrid, tblk>>>(Wk, WkH, WkL);
    splitT_kernel<<<tgrid, tblk>>>(Wv, WvH, WvL);
    splitT_kernel<<<tgrid, tblk>>>(Wo, WoH, WoL);
    split_kernel<<<(MROWS * DM / 4 + 255) / 256, 256>>>(dec, decH, decL, MROWS * DM);
    split_kernel<<<(BB * LK * DM / 4 + 255) / 256, 256>>>(enc, encH, encL, BB * LK * DM);

    // projections
    bgemm<<<dim3(DM / 128, MROWS / 128), 256>>>(decH, decL, WqH, WqL, Qs, MROWS, DM, DM);
    bgemm<<<dim3(DM / 128, BB * LK / 128), 256>>>(encH, encL, WkH, WkL, Ks, BB * LK, DM, DM);
    bgemm<<<dim3(DM / 128, BB * LK / 128), 256>>>(encH, encL, WvH, WvL, Vs, BB * LK, DM, DM);

    // flash-input splits
    split_kernel<<<(MROWS * DM / 4 + 255) / 256, 256>>>(Qs, QH, QL, MROWS * DM);
    split_kernel<<<(BB * LK * DM / 4 + 255) / 256, 256>>>(Ks, KH, KL, BB * LK * DM);
    vtsplit_kernel<<<dim3(LK / 32, NH * 2, BB), tblk>>>(Vs, VTH, VTL);

    // branch 0: dense SDP (tensor-core flash)
    flash_mma<<<dim3(LQ / 64, NH, BB), 128>>>(QH, QL, KH, KL, VTH, VTL, bo, 0);

    // branches 1 & 3: linear + cosine (single KV pass)
    kvchunk2_kernel<<<dim3(8, NH, BB), 256>>>(Ks, Vs, kvp, ksp);
    kvreduce_kernel<<<(2 * NKV + 255) / 256, 256>>>(kvp, kv, 2 * NKV);
    kvreduce_kernel<<<(2 * NKS + 255) / 256, 256>>>(ksp, ks, 2 * NKS);
    lin_out_kernel<<<dim3(LQ, NH, BB), 64>>>(Qs, kv, ks, bo + 1 * BSTR, 0);
    lin_out_kernel<<<dim3(LQ, NH, BB), 64>>>(Qs, kv + NKV, ks + NKS, bo + 3 * BSTR, 1);

    // branch 2: probsparse
    psparse_m_kernel<<<dim3(LQ / 128, NH, BB), 128>>>(Qs, Ks, sidx, nsample, Mv);
    topk_kernel<<<BB * NH, 256>>>(Mv, tp);
    vmean_part_kernel<<<dim3(16, BB * NH), 64>>>(Vs, vmp);
    vmean_reduce_kernel<<<(BB * NH * HD) / 64, 64>>>(vmp, vm);
    fill_vmean_kernel<<<(BB * LQ * DM + 255) / 256, 256>>>(vm, bo + 2 * BSTR);
    flash_kernel<<<dim3(1, NH, BB), 256, FSMEM>>>(Qs, Ks, Vs, bo + 2 * BSTR, tp);

    // branch 4: local windowed (tensor-core flash)
    flash_mma<<<dim3(LQ / 64, NH, BB), 128>>>(QH, QL, KH, KL, VTH, VTL, bo + 4 * BSTR, 1);

    // batched output projection
    split_kernel<<<(NBR * MROWS * DM / 4 + 255) / 256, 256>>>(bo, boH, boL, NBR * MROWS * DM);
    bgemm<<<dim3(DM / 128, NBR * MROWS / 128), 256>>>(boH, boL, WoH, WoL, pj, NBR * MROWS, DM, DM);

    // fused epilogue
    epilogue_kernel<<<MROWS, 256>>>(dec, pj, rmsw, alphas, out);
}